// round 5
// baseline (speedup 1.0000x reference)
#include <cuda_runtime.h>
#include <cuda_bf16.h>
#include <cstdint>

#define M_TOK 16384   // B*S
#define E_DIM 1024
#define NQ    64

// ---------------- scratch (__device__ globals; no allocs) ----------------
__device__ float         g_attn[(size_t)M_TOK * E_DIM];
__device__ float         g_x1[(size_t)M_TOK * E_DIM];
__device__ __nv_bfloat16 g_zhi[(size_t)M_TOK * E_DIM];
__device__ __nv_bfloat16 g_zlo[(size_t)M_TOK * E_DIM];
__device__ __nv_bfloat16 g_whi[(size_t)E_DIM * E_DIM];
__device__ __nv_bfloat16 g_wlo[(size_t)E_DIM * E_DIM];
__device__ __nv_bfloat16 g_w2hi[(size_t)E_DIM * NQ];
__device__ __nv_bfloat16 g_w2lo[(size_t)E_DIM * NQ];
__device__ __nv_bfloat16 g_qhi[(size_t)M_TOK * NQ];
__device__ __nv_bfloat16 g_qlo[(size_t)M_TOK * NQ];

// ---------------- PTX helpers (compute_100-safe) -------------------------
__device__ __forceinline__ uint32_t smem_u32(const void* p) {
    uint32_t a;
    asm("{ .reg .u64 t; cvta.to.shared.u64 t, %1; cvt.u32.u64 %0, t; }" : "=r"(a) : "l"(p));
    return a;
}
__device__ __forceinline__ void cp16(uint32_t dst, const void* src) {
    asm volatile("cp.async.cg.shared.global [%0], [%1], 16;" :: "r"(dst), "l"(src));
}
#define CP_COMMIT() asm volatile("cp.async.commit_group;" ::: "memory")
#define CP_WAIT2()  asm volatile("cp.async.wait_group 2;" ::: "memory")
#define CP_WAIT0()  asm volatile("cp.async.wait_group 0;" ::: "memory")

#define LDSM4(r, addr)                                                        \
    asm volatile("ldmatrix.sync.aligned.m8n8.x4.shared.b16 {%0,%1,%2,%3}, [%4];" \
        : "=r"((r)[0]), "=r"((r)[1]), "=r"((r)[2]), "=r"((r)[3]) : "r"(addr))

#define MMA16816(d, a, b)                                                     \
    asm volatile("mma.sync.aligned.m16n8k16.row.col.f32.bf16.bf16.f32 "       \
        "{%0,%1,%2,%3}, {%4,%5,%6,%7}, {%8,%9}, {%0,%1,%2,%3};"               \
        : "+f"((d)[0]), "+f"((d)[1]), "+f"((d)[2]), "+f"((d)[3])              \
        : "r"((a)[0]), "r"((a)[1]), "r"((a)[2]), "r"((a)[3]),                 \
          "r"((b)[0]), "r"((b)[1]))

// ---------------- bf16-split GEMM: C = A*B^T + bias ----------------------
// CTA 128x128, 8 warps (2x4), warp tile 64x32, BK=32.
// 4-stage cp.async pipeline, ONE __syncthreads per K-iteration.
// 160KB smem -> exactly 1 CTA/SM -> grid 1024 = 6.92 waves (98.8% balance).
#define BM 128
#define BN 128
#define BK 32
#define ROWB 80                      // smem row stride bytes (64 data + 16 pad)
#define MAT_B (128 * ROWB)           // bytes per 128x32 bf16 tile
#define STG   (4 * MAT_B)            // Ah, Al, Bh, Bl = 40960 B
#define NSTAGE 4
#define SM_BIAS (NSTAGE * STG)
#define SM_TOT  (SM_BIAS + BN * 4)

__global__ __launch_bounds__(256) void mma_gemm(
    const __nv_bfloat16* __restrict__ Ahi, const __nv_bfloat16* __restrict__ Alo,
    const __nv_bfloat16* __restrict__ Bhi, const __nv_bfloat16* __restrict__ Blo,
    const float* __restrict__ bias, float* __restrict__ Cout, int K) {
    extern __shared__ char smem[];
    const uint32_t sbase = smem_u32(smem);
    float* sbias = (float*)(smem + SM_BIAS);
    const int tid = threadIdx.x, wid = tid >> 5, lane = tid & 31;
    const int m0 = blockIdx.y * BM, n0 = blockIdx.x * BN;
    const int m_off = (wid & 1) * 64;        // warps 2x4, warp tile 64x32
    const int n_off = (wid >> 1) * 32;

    if (tid < BN) sbias[tid] = bias[n0 + tid];

    const uint32_t aRow = (uint32_t)(m_off + (lane & 15)) * ROWB + (lane >> 4) * 16;
    const uint32_t bRow = (uint32_t)(n_off + ((lane >> 4) << 3) + (lane & 7)) * ROWB
                        + ((lane >> 3) & 1) * 16;

    float acc[4][4][4] = {};

    const int C = K / BK;

    // guarded stage load: issues nothing past end of K, always commits a group
    auto load_stage = [&](int ki) {
        if (ki < C) {
            uint32_t sb = sbase + (ki & (NSTAGE - 1)) * STG;
            int kc0 = ki * BK;
            #pragma unroll
            for (int i = 0; i < 2; ++i) {
                int c = tid + i * 256;               // 512 16B-chunks per matrix
                int r = c >> 2, ch = c & 3;
                uint32_t d = (uint32_t)r * ROWB + ch * 16;
                size_t goA = (size_t)(m0 + r) * K + kc0 + ch * 8;
                size_t goB = (size_t)(n0 + r) * K + kc0 + ch * 8;
                cp16(sb + d,             Ahi + goA);
                cp16(sb + MAT_B + d,     Alo + goA);
                cp16(sb + 2 * MAT_B + d, Bhi + goB);
                cp16(sb + 3 * MAT_B + d, Blo + goB);
            }
        }
        CP_COMMIT();
    };

    // prologue: stages 0..2 in flight
    load_stage(0);
    load_stage(1);
    load_stage(2);

    for (int ki = 0; ki < C; ++ki) {
        CP_WAIT2();              // group ki complete (<=2 of {ki+1,ki+2} pending)
        __syncthreads();         // all warps done reading stage (ki-1)&3
        load_stage(ki + 3);      // overwrites stage (ki-1)&3 — now dead

        uint32_t base = sbase + (ki & (NSTAGE - 1)) * STG;
        uint32_t aH = base + aRow;
        uint32_t aL = aH + MAT_B;
        uint32_t bH = base + 2 * MAT_B + bRow;
        uint32_t bL = bH + MAT_B;

        #pragma unroll
        for (int ks = 0; ks < 2; ++ks) {         // two k16 steps per BK=32
            uint32_t ah[4][4], al[4][4], bh[4][2], bl[4][2];
            #pragma unroll
            for (int mi = 0; mi < 4; ++mi) {
                LDSM4(ah[mi], aH + ks * 32 + mi * 16 * ROWB);
                LDSM4(al[mi], aL + ks * 32 + mi * 16 * ROWB);
            }
            #pragma unroll
            for (int p = 0; p < 2; ++p) {        // each x4 covers two n8 groups
                uint32_t t[4];
                LDSM4(t, bH + ks * 32 + p * 16 * ROWB);
                bh[2 * p][0] = t[0]; bh[2 * p][1] = t[1];
                bh[2 * p + 1][0] = t[2]; bh[2 * p + 1][1] = t[3];
                LDSM4(t, bL + ks * 32 + p * 16 * ROWB);
                bl[2 * p][0] = t[0]; bl[2 * p][1] = t[1];
                bl[2 * p + 1][0] = t[2]; bl[2 * p + 1][1] = t[3];
            }
            #pragma unroll
            for (int mi = 0; mi < 4; ++mi)
                #pragma unroll
                for (int ni = 0; ni < 4; ++ni) {
                    MMA16816(acc[mi][ni], ah[mi], bh[ni]);
                    MMA16816(acc[mi][ni], ah[mi], bl[ni]);
                    MMA16816(acc[mi][ni], al[mi], bh[ni]);
                }
        }
    }
    CP_WAIT0();

    // epilogue
    #pragma unroll
    for (int mi = 0; mi < 4; ++mi) {
        int m = m0 + m_off + mi * 16 + (lane >> 2);
        #pragma unroll
        for (int ni = 0; ni < 4; ++ni) {
            int nl = n_off + ni * 8 + 2 * (lane & 3);
            float2 bv = *(float2*)&sbias[nl];
            float* p0 = Cout + (size_t)m * E_DIM + n0 + nl;
            float* p1 = p0 + 8 * E_DIM;
            float2 o0 = {acc[mi][ni][0] + bv.x, acc[mi][ni][1] + bv.y};
            float2 o1 = {acc[mi][ni][2] + bv.x, acc[mi][ni][3] + bv.y};
            *(float2*)p0 = o0;
            *(float2*)p1 = o1;
        }
    }
}

// ---------------- z = cos(x + a0[e%64])*cos(a1[e%64]), split to bf16 -----
union BPack { __nv_bfloat16 b[4]; uint2 u; };

__global__ __launch_bounds__(256) void z_split_kernel(const float* __restrict__ x,
                                                      const float* __restrict__ aqp,
                                                      __nv_bfloat16* __restrict__ zhi,
                                                      __nv_bfloat16* __restrict__ zlo) {
    __shared__ float sa0[NQ], sc1[NQ];
    if (threadIdx.x < NQ) {
        sa0[threadIdx.x] = aqp[threadIdx.x * 3 + 0];
        sc1[threadIdx.x] = __cosf(aqp[threadIdx.x * 3 + 1]);
    }
    __syncthreads();
    int i = blockIdx.x * blockDim.x + threadIdx.x;
    int d = (i * 4) & 63;
    float4 v = ((const float4*)x)[i];
    float z0 = __cosf(v.x + sa0[d + 0]) * sc1[d + 0];
    float z1 = __cosf(v.y + sa0[d + 1]) * sc1[d + 1];
    float z2 = __cosf(v.z + sa0[d + 2]) * sc1[d + 2];
    float z3 = __cosf(v.w + sa0[d + 3]) * sc1[d + 3];
    BPack h, l;
    h.b[0] = __float2bfloat16(z0); l.b[0] = __float2bfloat16(z0 - __bfloat162float(h.b[0]));
    h.b[1] = __float2bfloat16(z1); l.b[1] = __float2bfloat16(z1 - __bfloat162float(h.b[1]));
    h.b[2] = __float2bfloat16(z2); l.b[2] = __float2bfloat16(z2 - __bfloat162float(h.b[2]));
    h.b[3] = __float2bfloat16(z3); l.b[3] = __float2bfloat16(z3 - __bfloat162float(h.b[3]));
    ((uint2*)zhi)[i] = h.u;
    ((uint2*)zlo)[i] = l.u;
}

// ---------------- weight split ----------------
__global__ __launch_bounds__(256) void w_split_kernel(const float* __restrict__ w,
                                                      __nv_bfloat16* __restrict__ hi,
                                                      __nv_bfloat16* __restrict__ lo, int n) {
    for (int i = blockIdx.x * blockDim.x + threadIdx.x; i < n; i += gridDim.x * blockDim.x) {
        float v = w[i];
        __nv_bfloat16 h = __float2bfloat16(v);
        hi[i] = h;
        lo[i] = __float2bfloat16(v - __bfloat162float(h));
    }
}

// ---------------- LN1 + q split ----------------
__global__ __launch_bounds__(256) void ln1_kernel(const float* __restrict__ x,
                                                  const float* __restrict__ attn,
                                                  const float* __restrict__ w,
                                                  const float* __restrict__ b,
                                                  const float* __restrict__ fqp,
                                                  float* __restrict__ x1,
                                                  __nv_bfloat16* __restrict__ qhi,
                                                  __nv_bfloat16* __restrict__ qlo) {
    int row  = blockIdx.x * 8 + (threadIdx.x >> 5);
    int lane = threadIdx.x & 31;
    const float4* px = (const float4*)(x    + (size_t)row * E_DIM);
    const float4* pa = (const float4*)(attn + (size_t)row * E_DIM);
    float4 v[8];
    float s = 0.f, ss = 0.f;
    #pragma unroll
    for (int j = 0; j < 8; ++j) {
        float4 a = px[lane + j * 32];
        float4 t = pa[lane + j * 32];
        float4 u = {a.x + t.x, a.y + t.y, a.z + t.z, a.w + t.w};
        v[j] = u;
        s  += u.x + u.y + u.z + u.w;
        ss += u.x * u.x + u.y * u.y + u.z * u.z + u.w * u.w;
    }
    #pragma unroll
    for (int o = 16; o; o >>= 1) {
        s  += __shfl_xor_sync(0xffffffffu, s, o);
        ss += __shfl_xor_sync(0xffffffffu, ss, o);
    }
    float mu  = s * (1.f / E_DIM);
    float var = ss * (1.f / E_DIM) - mu * mu;
    float rs  = rsqrtf(var + 1e-5f);

    float4* po = (float4*)(x1 + (size_t)row * E_DIM);
    #pragma unroll
    for (int j = 0; j < 8; ++j) {
        int c4 = lane + j * 32;
        float4 wv = ((const float4*)w)[c4];
        float4 bv = ((const float4*)b)[c4];
        float4 u  = v[j];
        float4 o;
        o.x = (u.x - mu) * rs * wv.x + bv.x;
        o.y = (u.y - mu) * rs * wv.y + bv.y;
        o.z = (u.z - mu) * rs * wv.z + bv.z;
        o.w = (u.w - mu) * rs * wv.w + bv.w;
        po[c4] = o;
        if (j == 0 && lane < 16) {
            int k = lane * 4;
            float q0 = __cosf(o.x + fqp[(k + 0) * 3]) * __cosf(fqp[(k + 0) * 3 + 1]);
            float q1 = __cosf(o.y + fqp[(k + 1) * 3]) * __cosf(fqp[(k + 1) * 3 + 1]);
            float q2 = __cosf(o.z + fqp[(k + 2) * 3]) * __cosf(fqp[(k + 2) * 3 + 1]);
            float q3 = __cosf(o.w + fqp[(k + 3) * 3]) * __cosf(fqp[(k + 3) * 3 + 1]);
            BPack h, l;
            h.b[0] = __float2bfloat16(q0); l.b[0] = __float2bfloat16(q0 - __bfloat162float(h.b[0]));
            h.b[1] = __float2bfloat16(q1); l.b[1] = __float2bfloat16(q1 - __bfloat162float(h.b[1]));
            h.b[2] = __float2bfloat16(q2); l.b[2] = __float2bfloat16(q2 - __bfloat162float(h.b[2]));
            h.b[3] = __float2bfloat16(q3); l.b[3] = __float2bfloat16(q3 - __bfloat162float(h.b[3]));
            *(uint2*)(qhi + (size_t)row * NQ + k) = h.u;
            *(uint2*)(qlo + (size_t)row * NQ + k) = l.u;
        }
    }
}

// ---------------- LN2 ----------------
__global__ __launch_bounds__(256) void ln2_kernel(const float* __restrict__ x1,
                                                  const float* __restrict__ ffn,
                                                  const float* __restrict__ w,
                                                  const float* __restrict__ b,
                                                  float* __restrict__ out) {
    int row  = blockIdx.x * 8 + (threadIdx.x >> 5);
    int lane = threadIdx.x & 31;
    const float4* px = (const float4*)(x1  + (size_t)row * E_DIM);
    const float4* pf = (const float4*)(ffn + (size_t)row * E_DIM);
    float4 v[8];
    float s = 0.f, ss = 0.f;
    #pragma unroll
    for (int j = 0; j < 8; ++j) {
        float4 a = px[lane + j * 32];
        float4 t = pf[lane + j * 32];
        float4 u = {a.x + t.x, a.y + t.y, a.z + t.z, a.w + t.w};
        v[j] = u;
        s  += u.x + u.y + u.z + u.w;
        ss += u.x * u.x + u.y * u.y + u.z * u.z + u.w * u.w;
    }
    #pragma unroll
    for (int o = 16; o; o >>= 1) {
        s  += __shfl_xor_sync(0xffffffffu, s, o);
        ss += __shfl_xor_sync(0xffffffffu, ss, o);
    }
    float mu  = s * (1.f / E_DIM);
    float var = ss * (1.f / E_DIM) - mu * mu;
    float rs  = rsqrtf(var + 1e-5f);

    float4* po = (float4*)(out + (size_t)row * E_DIM);
    #pragma unroll
    for (int j = 0; j < 8; ++j) {
        int c4 = lane + j * 32;
        float4 wv = ((const float4*)w)[c4];
        float4 bv = ((const float4*)b)[c4];
        float4 u  = v[j];
        float4 o;
        o.x = (u.x - mu) * rs * wv.x + bv.x;
        o.y = (u.y - mu) * rs * wv.y + bv.y;
        o.z = (u.z - mu) * rs * wv.z + bv.z;
        o.w = (u.w - mu) * rs * wv.w + bv.w;
        po[c4] = o;
    }
}

// ---------------- launcher ----------------
extern "C" void kernel_launch(void* const* d_in, const int* in_sizes, int n_in,
                              void* d_out, int out_size) {
    const float* x   = (const float*)d_in[0];
    const float* aqp = (const float*)d_in[1];
    const float* opw = (const float*)d_in[2];
    const float* opb = (const float*)d_in[3];
    const float* fqp = (const float*)d_in[4];
    const float* flw = (const float*)d_in[5];
    const float* flb = (const float*)d_in[6];
    const float* n1w = (const float*)d_in[7];
    const float* n1b = (const float*)d_in[8];
    const float* n2w = (const float*)d_in[9];
    const float* n2b = (const float*)d_in[10];
    float* out = (float*)d_out;

    float *attn, *x1;
    __nv_bfloat16 *zhi, *zlo, *whi, *wlo, *w2hi, *w2lo, *qhi, *qlo;
    cudaGetSymbolAddress((void**)&attn, g_attn);
    cudaGetSymbolAddress((void**)&x1,   g_x1);
    cudaGetSymbolAddress((void**)&zhi,  g_zhi);
    cudaGetSymbolAddress((void**)&zlo,  g_zlo);
    cudaGetSymbolAddress((void**)&whi,  g_whi);
    cudaGetSymbolAddress((void**)&wlo,  g_wlo);
    cudaGetSymbolAddress((void**)&w2hi, g_w2hi);
    cudaGetSymbolAddress((void**)&w2lo, g_w2lo);
    cudaGetSymbolAddress((void**)&qhi,  g_qhi);
    cudaGetSymbolAddress((void**)&qlo,  g_qlo);

    cudaFuncSetAttribute(mma_gemm, cudaFuncAttributeMaxDynamicSharedMemorySize, SM_TOT);

    // 1) z -> (zhi, zlo)
    z_split_kernel<<<(M_TOK * E_DIM / 4) / 256, 256>>>(x, aqp, zhi, zlo);
    // 2) weight splits
    w_split_kernel<<<2048, 256>>>(opw, whi, wlo, E_DIM * E_DIM);
    w_split_kernel<<<256, 256>>>(flw, w2hi, w2lo, E_DIM * NQ);
    // 3) attn = z @ opw^T + opb
    dim3 g1(E_DIM / BN, M_TOK / BM);
    mma_gemm<<<g1, 256, SM_TOT>>>(zhi, zlo, whi, wlo, opb, attn, E_DIM);
    // 4) x1 = LN1(x + attn); q -> (qhi, qlo)
    ln1_kernel<<<M_TOK / 8, 256>>>(x, attn, n1w, n1b, fqp, x1, qhi, qlo);
    // 5) ffn = q @ flw^T + flb   (K = 64)
    mma_gemm<<<g1, 256, SM_TOT>>>(qhi, qlo, w2hi, w2lo, flb, attn, NQ);
    // 6) out = LN2(x1 + ffn)
    ln2_kernel<<<M_TOK / 8, 256>>>(x1, attn, n2w, n2b, out);
}

// round 6
// speedup vs baseline: 1.4840x; 1.4840x over previous
#include <cuda_runtime.h>
#include <cuda_fp16.h>
#include <cstdint>

#define M_TOK 16384   // B*S
#define E_DIM 1024
#define NQ    64

// ---------------- scratch (__device__ globals; no allocs) ----------------
__device__ float  g_attn[(size_t)M_TOK * E_DIM];
__device__ float  g_x1[(size_t)M_TOK * E_DIM];
__device__ __half g_zh[(size_t)M_TOK * E_DIM];     // A of GEMM1 (fp16, no residual)
__device__ __half g_whi[(size_t)E_DIM * E_DIM];
__device__ __half g_wlo[(size_t)E_DIM * E_DIM];
__device__ __half g_w2hi[(size_t)E_DIM * NQ];
__device__ __half g_w2lo[(size_t)E_DIM * NQ];
__device__ __half g_qh[(size_t)M_TOK * NQ];        // A of GEMM2

// ---------------- PTX helpers (compute_100-safe) -------------------------
__device__ __forceinline__ uint32_t smem_u32(const void* p) {
    uint32_t a;
    asm("{ .reg .u64 t; cvta.to.shared.u64 t, %1; cvt.u32.u64 %0, t; }" : "=r"(a) : "l"(p));
    return a;
}
__device__ __forceinline__ void cp16(uint32_t dst, const void* src) {
    asm volatile("cp.async.cg.shared.global [%0], [%1], 16;" :: "r"(dst), "l"(src));
}
#define CP_COMMIT() asm volatile("cp.async.commit_group;" ::: "memory")
#define CP_WAIT1()  asm volatile("cp.async.wait_group 1;" ::: "memory")
#define CP_WAIT0()  asm volatile("cp.async.wait_group 0;" ::: "memory")

#define LDSM4(r, addr)                                                        \
    asm volatile("ldmatrix.sync.aligned.m8n8.x4.shared.b16 {%0,%1,%2,%3}, [%4];" \
        : "=r"((r)[0]), "=r"((r)[1]), "=r"((r)[2]), "=r"((r)[3]) : "r"(addr))

#define MMA16816(d, a, b)                                                     \
    asm volatile("mma.sync.aligned.m16n8k16.row.col.f32.f16.f16.f32 "         \
        "{%0,%1,%2,%3}, {%4,%5,%6,%7}, {%8,%9}, {%0,%1,%2,%3};"               \
        : "+f"((d)[0]), "+f"((d)[1]), "+f"((d)[2]), "+f"((d)[3])              \
        : "r"((a)[0]), "r"((a)[1]), "r"((a)[2]), "r"((a)[3]),                 \
          "r"((b)[0]), "r"((b)[1]))

// ---------------- fp16 2-term GEMM: C = A*(Bh+Bl)^T + bias ---------------
// A fp16 [M,K] row-major; Bh,Bl fp16 [N,K] row-major (B = Bh+Bl exactly-ish).
// CTA 128x128, 8 warps (2x4), warp tile 64x32, BK=32, 2-stage cp.async,
// 2 CTAs/SM (the empirically best residency).
#define BM 128
#define BN 128
#define BK 32
#define ROWB 80                      // smem row stride bytes (64 data + 16 pad)
#define MAT_B (128 * ROWB)           // bytes per 128x32 fp16 tile
#define STG   (3 * MAT_B)            // Ah, Bh, Bl = 30720 B
#define SM_BIAS (2 * STG)
#define SM_TOT  (SM_BIAS + BN * 4)

__global__ __launch_bounds__(256, 2) void mma_gemm(
    const __half* __restrict__ Ah,
    const __half* __restrict__ Bhi, const __half* __restrict__ Blo,
    const float* __restrict__ bias, float* __restrict__ Cout, int K) {
    extern __shared__ char smem[];
    const uint32_t sbase = smem_u32(smem);
    float* sbias = (float*)(smem + SM_BIAS);
    const int tid = threadIdx.x, wid = tid >> 5, lane = tid & 31;
    const int m0 = blockIdx.y * BM, n0 = blockIdx.x * BN;
    const int m_off = (wid & 1) * 64;        // warps 2x4, warp tile 64x32
    const int n_off = (wid >> 1) * 32;

    if (tid < BN) sbias[tid] = bias[n0 + tid];

    const uint32_t aRow = (uint32_t)(m_off + (lane & 15)) * ROWB + (lane >> 4) * 16;
    const uint32_t bRow = (uint32_t)(n_off + ((lane >> 4) << 3) + (lane & 7)) * ROWB
                        + ((lane >> 3) & 1) * 16;

    float acc[4][4][4] = {};

    auto load_stage = [&](int s, int kc0) {
        uint32_t sb = sbase + s * STG;
        #pragma unroll
        for (int i = 0; i < 2; ++i) {
            int c = tid + i * 256;               // 512 16B-chunks per matrix
            int r = c >> 2, ch = c & 3;
            uint32_t d = (uint32_t)r * ROWB + ch * 16;
            size_t goA = (size_t)(m0 + r) * K + kc0 + ch * 8;
            size_t goB = (size_t)(n0 + r) * K + kc0 + ch * 8;
            cp16(sb + d,             Ah  + goA);
            cp16(sb + MAT_B + d,     Bhi + goB);
            cp16(sb + 2 * MAT_B + d, Blo + goB);
        }
        CP_COMMIT();
    };

    const int C = K / BK;
    load_stage(0, 0);

    for (int ki = 0; ki < C; ++ki) {
        int cur = ki & 1;
        if (ki + 1 < C) { load_stage(cur ^ 1, (ki + 1) * BK); CP_WAIT1(); }
        else           { CP_WAIT0(); }
        __syncthreads();

        uint32_t base = sbase + cur * STG;
        uint32_t aH = base + aRow;
        uint32_t bH = base + MAT_B + bRow;
        uint32_t bL = bH + MAT_B;

        #pragma unroll
        for (int ks = 0; ks < 2; ++ks) {         // two k16 steps per BK=32
            uint32_t ah[4][4], bh[4][2], bl[4][2];
            #pragma unroll
            for (int mi = 0; mi < 4; ++mi)
                LDSM4(ah[mi], aH + ks * 32 + mi * 16 * ROWB);
            #pragma unroll
            for (int p = 0; p < 2; ++p) {        // each x4 covers two n8 groups
                uint32_t t[4];
                LDSM4(t, bH + ks * 32 + p * 16 * ROWB);
                bh[2 * p][0] = t[0]; bh[2 * p][1] = t[1];
                bh[2 * p + 1][0] = t[2]; bh[2 * p + 1][1] = t[3];
                LDSM4(t, bL + ks * 32 + p * 16 * ROWB);
                bl[2 * p][0] = t[0]; bl[2 * p][1] = t[1];
                bl[2 * p + 1][0] = t[2]; bl[2 * p + 1][1] = t[3];
            }
            #pragma unroll
            for (int mi = 0; mi < 4; ++mi)
                #pragma unroll
                for (int ni = 0; ni < 4; ++ni) {
                    MMA16816(acc[mi][ni], ah[mi], bh[ni]);
                    MMA16816(acc[mi][ni], ah[mi], bl[ni]);
                }
        }
        __syncthreads();
    }

    // epilogue
    #pragma unroll
    for (int mi = 0; mi < 4; ++mi) {
        int m = m0 + m_off + mi * 16 + (lane >> 2);
        #pragma unroll
        for (int ni = 0; ni < 4; ++ni) {
            int nl = n_off + ni * 8 + 2 * (lane & 3);
            float2 bv = *(float2*)&sbias[nl];
            float* p0 = Cout + (size_t)m * E_DIM + n0 + nl;
            float* p1 = p0 + 8 * E_DIM;
            float2 o0 = {acc[mi][ni][0] + bv.x, acc[mi][ni][1] + bv.y};
            float2 o1 = {acc[mi][ni][2] + bv.x, acc[mi][ni][3] + bv.y};
            *(float2*)p0 = o0;
            *(float2*)p1 = o1;
        }
    }
}

// ---------------- z = cos(x + a0[e%64])*cos(a1[e%64]) -> fp16 ------------
union HPack { __half h[4]; uint2 u; };

__global__ __launch_bounds__(256) void z_half_kernel(const float* __restrict__ x,
                                                     const float* __restrict__ aqp,
                                                     __half* __restrict__ zh) {
    __shared__ float sa0[NQ], sc1[NQ];
    if (threadIdx.x < NQ) {
        sa0[threadIdx.x] = aqp[threadIdx.x * 3 + 0];
        sc1[threadIdx.x] = __cosf(aqp[threadIdx.x * 3 + 1]);
    }
    __syncthreads();
    int i = blockIdx.x * blockDim.x + threadIdx.x;
    int d = (i * 4) & 63;
    float4 v = ((const float4*)x)[i];
    HPack h;
    h.h[0] = __float2half(__cosf(v.x + sa0[d + 0]) * sc1[d + 0]);
    h.h[1] = __float2half(__cosf(v.y + sa0[d + 1]) * sc1[d + 1]);
    h.h[2] = __float2half(__cosf(v.z + sa0[d + 2]) * sc1[d + 2]);
    h.h[3] = __float2half(__cosf(v.w + sa0[d + 3]) * sc1[d + 3]);
    ((uint2*)zh)[i] = h.u;
}

// ---------------- weight split to fp16 hi/lo ----------------
__global__ __launch_bounds__(256) void w_split_kernel(const float* __restrict__ w,
                                                      __half* __restrict__ hi,
                                                      __half* __restrict__ lo, int n) {
    for (int i = blockIdx.x * blockDim.x + threadIdx.x; i < n; i += gridDim.x * blockDim.x) {
        float v = w[i];
        __half h = __float2half(v);
        hi[i] = h;
        lo[i] = __float2half(v - __half2float(h));
    }
}

// ---------------- LN1 + q (fp16) ----------------
__global__ __launch_bounds__(256) void ln1_kernel(const float* __restrict__ x,
                                                  const float* __restrict__ attn,
                                                  const float* __restrict__ w,
                                                  const float* __restrict__ b,
                                                  const float* __restrict__ fqp,
                                                  float* __restrict__ x1,
                                                  __half* __restrict__ qh) {
    int row  = blockIdx.x * 8 + (threadIdx.x >> 5);
    int lane = threadIdx.x & 31;
    const float4* px = (const float4*)(x    + (size_t)row * E_DIM);
    const float4* pa = (const float4*)(attn + (size_t)row * E_DIM);
    float4 v[8];
    float s = 0.f, ss = 0.f;
    #pragma unroll
    for (int j = 0; j < 8; ++j) {
        float4 a = px[lane + j * 32];
        float4 t = pa[lane + j * 32];
        float4 u = {a.x + t.x, a.y + t.y, a.z + t.z, a.w + t.w};
        v[j] = u;
        s  += u.x + u.y + u.z + u.w;
        ss += u.x * u.x + u.y * u.y + u.z * u.z + u.w * u.w;
    }
    #pragma unroll
    for (int o = 16; o; o >>= 1) {
        s  += __shfl_xor_sync(0xffffffffu, s, o);
        ss += __shfl_xor_sync(0xffffffffu, ss, o);
    }
    float mu  = s * (1.f / E_DIM);
    float var = ss * (1.f / E_DIM) - mu * mu;
    float rs  = rsqrtf(var + 1e-5f);

    float4* po = (float4*)(x1 + (size_t)row * E_DIM);
    #pragma unroll
    for (int j = 0; j < 8; ++j) {
        int c4 = lane + j * 32;
        float4 wv = ((const float4*)w)[c4];
        float4 bv = ((const float4*)b)[c4];
        float4 u  = v[j];
        float4 o;
        o.x = (u.x - mu) * rs * wv.x + bv.x;
        o.y = (u.y - mu) * rs * wv.y + bv.y;
        o.z = (u.z - mu) * rs * wv.z + bv.z;
        o.w = (u.w - mu) * rs * wv.w + bv.w;
        po[c4] = o;
        if (j == 0 && lane < 16) {
            int k = lane * 4;
            HPack h;
            h.h[0] = __float2half(__cosf(o.x + fqp[(k + 0) * 3]) * __cosf(fqp[(k + 0) * 3 + 1]));
            h.h[1] = __float2half(__cosf(o.y + fqp[(k + 1) * 3]) * __cosf(fqp[(k + 1) * 3 + 1]));
            h.h[2] = __float2half(__cosf(o.z + fqp[(k + 2) * 3]) * __cosf(fqp[(k + 2) * 3 + 1]));
            h.h[3] = __float2half(__cosf(o.w + fqp[(k + 3) * 3]) * __cosf(fqp[(k + 3) * 3 + 1]));
            *(uint2*)(qh + (size_t)row * NQ + k) = h.u;
        }
    }
}

// ---------------- LN2 ----------------
__global__ __launch_bounds__(256) void ln2_kernel(const float* __restrict__ x1,
                                                  const float* __restrict__ ffn,
                                                  const float* __restrict__ w,
                                                  const float* __restrict__ b,
                                                  float* __restrict__ out) {
    int row  = blockIdx.x * 8 + (threadIdx.x >> 5);
    int lane = threadIdx.x & 31;
    const float4* px = (const float4*)(x1  + (size_t)row * E_DIM);
    const float4* pf = (const float4*)(ffn + (size_t)row * E_DIM);
    float4 v[8];
    float s = 0.f, ss = 0.f;
    #pragma unroll
    for (int j = 0; j < 8; ++j) {
        float4 a = px[lane + j * 32];
        float4 t = pf[lane + j * 32];
        float4 u = {a.x + t.x, a.y + t.y, a.z + t.z, a.w + t.w};
        v[j] = u;
        s  += u.x + u.y + u.z + u.w;
        ss += u.x * u.x + u.y * u.y + u.z * u.z + u.w * u.w;
    }
    #pragma unroll
    for (int o = 16; o; o >>= 1) {
        s  += __shfl_xor_sync(0xffffffffu, s, o);
        ss += __shfl_xor_sync(0xffffffffu, ss, o);
    }
    float mu  = s * (1.f / E_DIM);
    float var = ss * (1.f / E_DIM) - mu * mu;
    float rs  = rsqrtf(var + 1e-5f);

    float4* po = (float4*)(out + (size_t)row * E_DIM);
    #pragma unroll
    for (int j = 0; j < 8; ++j) {
        int c4 = lane + j * 32;
        float4 wv = ((const float4*)w)[c4];
        float4 bv = ((const float4*)b)[c4];
        float4 u  = v[j];
        float4 o;
        o.x = (u.x - mu) * rs * wv.x + bv.x;
        o.y = (u.y - mu) * rs * wv.y + bv.y;
        o.z = (u.z - mu) * rs * wv.z + bv.z;
        o.w = (u.w - mu) * rs * wv.w + bv.w;
        po[c4] = o;
    }
}

// ---------------- launcher ----------------
extern "C" void kernel_launch(void* const* d_in, const int* in_sizes, int n_in,
                              void* d_out, int out_size) {
    const float* x   = (const float*)d_in[0];
    const float* aqp = (const float*)d_in[1];
    const float* opw = (const float*)d_in[2];
    const float* opb = (const float*)d_in[3];
    const float* fqp = (const float*)d_in[4];
    const float* flw = (const float*)d_in[5];
    const float* flb = (const float*)d_in[6];
    const float* n1w = (const float*)d_in[7];
    const float* n1b = (const float*)d_in[8];
    const float* n2w = (const float*)d_in[9];
    const float* n2b = (const float*)d_in[10];
    float* out = (float*)d_out;

    float *attn, *x1;
    __half *zh, *whi, *wlo, *w2hi, *w2lo, *qh;
    cudaGetSymbolAddress((void**)&attn, g_attn);
    cudaGetSymbolAddress((void**)&x1,   g_x1);
    cudaGetSymbolAddress((void**)&zh,   g_zh);
    cudaGetSymbolAddress((void**)&whi,  g_whi);
    cudaGetSymbolAddress((void**)&wlo,  g_wlo);
    cudaGetSymbolAddress((void**)&w2hi, g_w2hi);
    cudaGetSymbolAddress((void**)&w2lo, g_w2lo);
    cudaGetSymbolAddress((void**)&qh,   g_qh);

    cudaFuncSetAttribute(mma_gemm, cudaFuncAttributeMaxDynamicSharedMemorySize, SM_TOT);

    // 1) z -> fp16
    z_half_kernel<<<(M_TOK * E_DIM / 4) / 256, 256>>>(x, aqp, zh);
    // 2) weight splits (fp16 hi/lo)
    w_split_kernel<<<2048, 256>>>(opw, whi, wlo, E_DIM * E_DIM);
    w_split_kernel<<<256, 256>>>(flw, w2hi, w2lo, E_DIM * NQ);
    // 3) attn = z @ opw^T + opb
    dim3 g1(E_DIM / BN, M_TOK / BM);
    mma_gemm<<<g1, 256, SM_TOT>>>(zh, whi, wlo, opb, attn, E_DIM);
    // 4) x1 = LN1(x + attn); q -> fp16
    ln1_kernel<<<M_TOK / 8, 256>>>(x, attn, n1w, n1b, fqp, x1, qh);
    // 5) ffn = q @ flw^T + flb   (K = 64)
    mma_gemm<<<g1, 256, SM_TOT>>>(qh, w2hi, w2lo, flb, attn, NQ);
    // 6) out = LN2(x1 + ffn)
    ln2_kernel<<<M_TOK / 8, 256>>>(x1, attn, n2w, n2b, out);
}

// round 7
// speedup vs baseline: 1.9566x; 1.3185x over previous
#include <cuda_runtime.h>
#include <cuda_fp16.h>
#include <cstdint>

#define M_TOK 16384   // B*S
#define E_DIM 1024
#define NQ    64

// ---------------- scratch (__device__ globals; no allocs) ----------------
__device__ float  g_attn[(size_t)M_TOK * E_DIM];
__device__ float  g_x1[(size_t)M_TOK * E_DIM];
__device__ __half g_zh[(size_t)M_TOK * E_DIM];     // A of GEMM1
__device__ __half g_wh[(size_t)E_DIM * E_DIM];     // B of GEMM1
__device__ __half g_w2h[(size_t)E_DIM * NQ];       // B of GEMM2
__device__ __half g_qh[(size_t)M_TOK * NQ];        // A of GEMM2

// ---------------- PTX helpers (compute_100-safe) -------------------------
__device__ __forceinline__ uint32_t smem_u32(const void* p) {
    uint32_t a;
    asm("{ .reg .u64 t; cvta.to.shared.u64 t, %1; cvt.u32.u64 %0, t; }" : "=r"(a) : "l"(p));
    return a;
}
__device__ __forceinline__ void cp16(uint32_t dst, const void* src) {
    asm volatile("cp.async.cg.shared.global [%0], [%1], 16;" :: "r"(dst), "l"(src));
}
#define CP_COMMIT() asm volatile("cp.async.commit_group;" ::: "memory")
#define CP_WAIT1()  asm volatile("cp.async.wait_group 1;" ::: "memory")
#define CP_WAIT0()  asm volatile("cp.async.wait_group 0;" ::: "memory")

#define LDSM4(r, addr)                                                        \
    asm volatile("ldmatrix.sync.aligned.m8n8.x4.shared.b16 {%0,%1,%2,%3}, [%4];" \
        : "=r"((r)[0]), "=r"((r)[1]), "=r"((r)[2]), "=r"((r)[3]) : "r"(addr))

#define MMA16816(d, a, b)                                                     \
    asm volatile("mma.sync.aligned.m16n8k16.row.col.f32.f16.f16.f32 "         \
        "{%0,%1,%2,%3}, {%4,%5,%6,%7}, {%8,%9}, {%0,%1,%2,%3};"               \
        : "+f"((d)[0]), "+f"((d)[1]), "+f"((d)[2]), "+f"((d)[3])              \
        : "r"((a)[0]), "r"((a)[1]), "r"((a)[2]), "r"((a)[3]),                 \
          "r"((b)[0]), "r"((b)[1]))

// ---------------- fp16 GEMM: C = A*B^T + bias ----------------------------
// A fp16 [M,K] row-major; B fp16 [N,K] row-major.
// CTA 128x128, 8 warps (2x4), warp tile 64x32, BK=32, 2-stage cp.async,
// 2 CTAs/SM (empirically best residency).
#define BM 128
#define BN 128
#define BK 32
#define ROWB 80                      // smem row stride bytes (64 data + 16 pad)
#define MAT_B (128 * ROWB)           // bytes per 128x32 fp16 tile
#define STG   (2 * MAT_B)            // A, B = 20480 B per stage
#define SM_BIAS (2 * STG)
#define SM_TOT  (SM_BIAS + BN * 4)

__global__ __launch_bounds__(256, 2) void mma_gemm(
    const __half* __restrict__ Ah, const __half* __restrict__ Bh,
    const float* __restrict__ bias, float* __restrict__ Cout, int K) {
    extern __shared__ char smem[];
    const uint32_t sbase = smem_u32(smem);
    float* sbias = (float*)(smem + SM_BIAS);
    const int tid = threadIdx.x, wid = tid >> 5, lane = tid & 31;
    const int m0 = blockIdx.y * BM, n0 = blockIdx.x * BN;
    const int m_off = (wid & 1) * 64;        // warps 2x4, warp tile 64x32
    const int n_off = (wid >> 1) * 32;

    if (tid < BN) sbias[tid] = bias[n0 + tid];

    const uint32_t aRow = (uint32_t)(m_off + (lane & 15)) * ROWB + (lane >> 4) * 16;
    const uint32_t bRow = (uint32_t)(n_off + ((lane >> 4) << 3) + (lane & 7)) * ROWB
                        + ((lane >> 3) & 1) * 16;

    float acc[4][4][4] = {};

    auto load_stage = [&](int s, int kc0) {
        uint32_t sb = sbase + s * STG;
        #pragma unroll
        for (int i = 0; i < 2; ++i) {
            int c = tid + i * 256;               // 512 16B-chunks per matrix
            int r = c >> 2, ch = c & 3;
            uint32_t d = (uint32_t)r * ROWB + ch * 16;
            size_t goA = (size_t)(m0 + r) * K + kc0 + ch * 8;
            size_t goB = (size_t)(n0 + r) * K + kc0 + ch * 8;
            cp16(sb + d,         Ah + goA);
            cp16(sb + MAT_B + d, Bh + goB);
        }
        CP_COMMIT();
    };

    const int C = K / BK;
    load_stage(0, 0);

    for (int ki = 0; ki < C; ++ki) {
        int cur = ki & 1;
        if (ki + 1 < C) { load_stage(cur ^ 1, (ki + 1) * BK); CP_WAIT1(); }
        else           { CP_WAIT0(); }
        __syncthreads();

        uint32_t base = sbase + cur * STG;
        uint32_t aH = base + aRow;
        uint32_t bH = base + MAT_B + bRow;

        #pragma unroll
        for (int ks = 0; ks < 2; ++ks) {         // two k16 steps per BK=32
            uint32_t ah[4][4], bh[4][2];
            #pragma unroll
            for (int mi = 0; mi < 4; ++mi)
                LDSM4(ah[mi], aH + ks * 32 + mi * 16 * ROWB);
            #pragma unroll
            for (int p = 0; p < 2; ++p) {        // each x4 covers two n8 groups
                uint32_t t[4];
                LDSM4(t, bH + ks * 32 + p * 16 * ROWB);
                bh[2 * p][0] = t[0]; bh[2 * p][1] = t[1];
                bh[2 * p + 1][0] = t[2]; bh[2 * p + 1][1] = t[3];
            }
            #pragma unroll
            for (int mi = 0; mi < 4; ++mi)
                #pragma unroll
                for (int ni = 0; ni < 4; ++ni)
                    MMA16816(acc[mi][ni], ah[mi], bh[ni]);
        }
        __syncthreads();
    }

    // epilogue
    #pragma unroll
    for (int mi = 0; mi < 4; ++mi) {
        int m = m0 + m_off + mi * 16 + (lane >> 2);
        #pragma unroll
        for (int ni = 0; ni < 4; ++ni) {
            int nl = n_off + ni * 8 + 2 * (lane & 3);
            float2 bv = *(float2*)&sbias[nl];
            float* p0 = Cout + (size_t)m * E_DIM + n0 + nl;
            float* p1 = p0 + 8 * E_DIM;
            float2 o0 = {acc[mi][ni][0] + bv.x, acc[mi][ni][1] + bv.y};
            float2 o1 = {acc[mi][ni][2] + bv.x, acc[mi][ni][3] + bv.y};
            *(float2*)p0 = o0;
            *(float2*)p1 = o1;
        }
    }
}

// ---------------- z = cos(x + a0[e%64])*cos(a1[e%64]) -> fp16 ------------
union HPack { __half h[4]; uint2 u; };

__global__ __launch_bounds__(256) void z_half_kernel(const float* __restrict__ x,
                                                     const float* __restrict__ aqp,
                                                     __half* __restrict__ zh) {
    __shared__ float sa0[NQ], sc1[NQ];
    if (threadIdx.x < NQ) {
        sa0[threadIdx.x] = aqp[threadIdx.x * 3 + 0];
        sc1[threadIdx.x] = __cosf(aqp[threadIdx.x * 3 + 1]);
    }
    __syncthreads();
    int i = blockIdx.x * blockDim.x + threadIdx.x;
    int d = (i * 4) & 63;
    float4 v = ((const float4*)x)[i];
    HPack h;
    h.h[0] = __float2half(__cosf(v.x + sa0[d + 0]) * sc1[d + 0]);
    h.h[1] = __float2half(__cosf(v.y + sa0[d + 1]) * sc1[d + 1]);
    h.h[2] = __float2half(__cosf(v.z + sa0[d + 2]) * sc1[d + 2]);
    h.h[3] = __float2half(__cosf(v.w + sa0[d + 3]) * sc1[d + 3]);
    ((uint2*)zh)[i] = h.u;
}

// ---------------- weight -> fp16 ----------------
__global__ __launch_bounds__(256) void w_half_kernel(const float* __restrict__ w,
                                                     __half* __restrict__ h, int n) {
    for (int i = blockIdx.x * blockDim.x + threadIdx.x; i < n; i += gridDim.x * blockDim.x)
        h[i] = __float2half(w[i]);
}

// ---------------- LN1 + q (fp16) ----------------
__global__ __launch_bounds__(256) void ln1_kernel(const float* __restrict__ x,
                                                  const float* __restrict__ attn,
                                                  const float* __restrict__ w,
                                                  const float* __restrict__ b,
                                                  const float* __restrict__ fqp,
                                                  float* __restrict__ x1,
                                                  __half* __restrict__ qh) {
    int row  = blockIdx.x * 8 + (threadIdx.x >> 5);
    int lane = threadIdx.x & 31;
    const float4* px = (const float4*)(x    + (size_t)row * E_DIM);
    const float4* pa = (const float4*)(attn + (size_t)row * E_DIM);
    float4 v[8];
    float s = 0.f, ss = 0.f;
    #pragma unroll
    for (int j = 0; j < 8; ++j) {
        float4 a = px[lane + j * 32];
        float4 t = pa[lane + j * 32];
        float4 u = {a.x + t.x, a.y + t.y, a.z + t.z, a.w + t.w};
        v[j] = u;
        s  += u.x + u.y + u.z + u.w;
        ss += u.x * u.x + u.y * u.y + u.z * u.z + u.w * u.w;
    }
    #pragma unroll
    for (int o = 16; o; o >>= 1) {
        s  += __shfl_xor_sync(0xffffffffu, s, o);
        ss += __shfl_xor_sync(0xffffffffu, ss, o);
    }
    float mu  = s * (1.f / E_DIM);
    float var = ss * (1.f / E_DIM) - mu * mu;
    float rs  = rsqrtf(var + 1e-5f);

    float4* po = (float4*)(x1 + (size_t)row * E_DIM);
    #pragma unroll
    for (int j = 0; j < 8; ++j) {
        int c4 = lane + j * 32;
        float4 wv = ((const float4*)w)[c4];
        float4 bv = ((const float4*)b)[c4];
        float4 u  = v[j];
        float4 o;
        o.x = (u.x - mu) * rs * wv.x + bv.x;
        o.y = (u.y - mu) * rs * wv.y + bv.y;
        o.z = (u.z - mu) * rs * wv.z + bv.z;
        o.w = (u.w - mu) * rs * wv.w + bv.w;
        po[c4] = o;
        if (j == 0 && lane < 16) {
            int k = lane * 4;
            HPack h;
            h.h[0] = __float2half(__cosf(o.x + fqp[(k + 0) * 3]) * __cosf(fqp[(k + 0) * 3 + 1]));
            h.h[1] = __float2half(__cosf(o.y + fqp[(k + 1) * 3]) * __cosf(fqp[(k + 1) * 3 + 1]));
            h.h[2] = __float2half(__cosf(o.z + fqp[(k + 2) * 3]) * __cosf(fqp[(k + 2) * 3 + 1]));
            h.h[3] = __float2half(__cosf(o.w + fqp[(k + 3) * 3]) * __cosf(fqp[(k + 3) * 3 + 1]));
            *(uint2*)(qh + (size_t)row * NQ + k) = h.u;
        }
    }
}

// ---------------- LN2 ----------------
__global__ __launch_bounds__(256) void ln2_kernel(const float* __restrict__ x1,
                                                  const float* __restrict__ ffn,
                                                  const float* __restrict__ w,
                                                  const float* __restrict__ b,
                                                  float* __restrict__ out) {
    int row  = blockIdx.x * 8 + (threadIdx.x >> 5);
    int lane = threadIdx.x & 31;
    const float4* px = (const float4*)(x1  + (size_t)row * E_DIM);
    const float4* pf = (const float4*)(ffn + (size_t)row * E_DIM);
    float4 v[8];
    float s = 0.f, ss = 0.f;
    #pragma unroll
    for (int j = 0; j < 8; ++j) {
        float4 a = px[lane + j * 32];
        float4 t = pf[lane + j * 32];
        float4 u = {a.x + t.x, a.y + t.y, a.z + t.z, a.w + t.w};
        v[j] = u;
        s  += u.x + u.y + u.z + u.w;
        ss += u.x * u.x + u.y * u.y + u.z * u.z + u.w * u.w;
    }
    #pragma unroll
    for (int o = 16; o; o >>= 1) {
        s  += __shfl_xor_sync(0xffffffffu, s, o);
        ss += __shfl_xor_sync(0xffffffffu, ss, o);
    }
    float mu  = s * (1.f / E_DIM);
    float var = ss * (1.f / E_DIM) - mu * mu;
    float rs  = rsqrtf(var + 1e-5f);

    float4* po = (float4*)(out + (size_t)row * E_DIM);
    #pragma unroll
    for (int j = 0; j < 8; ++j) {
        int c4 = lane + j * 32;
        float4 wv = ((const float4*)w)[c4];
        float4 bv = ((const float4*)b)[c4];
        float4 u  = v[j];
        float4 o;
        o.x = (u.x - mu) * rs * wv.x + bv.x;
        o.y = (u.y - mu) * rs * wv.y + bv.y;
        o.z = (u.z - mu) * rs * wv.z + bv.z;
        o.w = (u.w - mu) * rs * wv.w + bv.w;
        po[c4] = o;
    }
}

// ---------------- launcher ----------------
extern "C" void kernel_launch(void* const* d_in, const int* in_sizes, int n_in,
                              void* d_out, int out_size) {
    const float* x   = (const float*)d_in[0];
    const float* aqp = (const float*)d_in[1];
    const float* opw = (const float*)d_in[2];
    const float* opb = (const float*)d_in[3];
    const float* fqp = (const float*)d_in[4];
    const float* flw = (const float*)d_in[5];
    const float* flb = (const float*)d_in[6];
    const float* n1w = (const float*)d_in[7];
    const float* n1b = (const float*)d_in[8];
    const float* n2w = (const float*)d_in[9];
    const float* n2b = (const float*)d_in[10];
    float* out = (float*)d_out;

    float *attn, *x1;
    __half *zh, *wh, *w2h, *qh;
    cudaGetSymbolAddress((void**)&attn, g_attn);
    cudaGetSymbolAddress((void**)&x1,   g_x1);
    cudaGetSymbolAddress((void**)&zh,   g_zh);
    cudaGetSymbolAddress((void**)&wh,   g_wh);
    cudaGetSymbolAddress((void**)&w2h,  g_w2h);
    cudaGetSymbolAddress((void**)&qh,   g_qh);

    cudaFuncSetAttribute(mma_gemm, cudaFuncAttributeMaxDynamicSharedMemorySize, SM_TOT);

    // 1) z -> fp16
    z_half_kernel<<<(M_TOK * E_DIM / 4) / 256, 256>>>(x, aqp, zh);
    // 2) weights -> fp16
    w_half_kernel<<<2048, 256>>>(opw, wh, E_DIM * E_DIM);
    w_half_kernel<<<256, 256>>>(flw, w2h, E_DIM * NQ);
    // 3) attn = z @ opw^T + opb
    dim3 g1(E_DIM / BN, M_TOK / BM);
    mma_gemm<<<g1, 256, SM_TOT>>>(zh, wh, opb, attn, E_DIM);
    // 4) x1 = LN1(x + attn); q -> fp16
    ln1_kernel<<<M_TOK / 8, 256>>>(x, attn, n1w, n1b, fqp, x1, qh);
    // 5) ffn = q @ flw^T + flb   (K = 64)
    mma_gemm<<<g1, 256, SM_TOT>>>(qh, w2h, flb, attn, NQ);
    // 6) out = LN2(x1 + ffn)
    ln2_kernel<<<M_TOK / 8, 256>>>(x1, attn, n2w, n2b, out);
}

// round 8
// speedup vs baseline: 2.0251x; 1.0350x over previous
#include <cuda_runtime.h>
#include <cuda_fp16.h>
#include <cstdint>

#define M_TOK 16384   // B*S
#define E_DIM 1024
#define NQ    64

// ---------------- scratch (__device__ globals; no allocs) ----------------
__device__ float  g_attn[(size_t)M_TOK * E_DIM];
__device__ float  g_x1[(size_t)M_TOK * E_DIM];
__device__ __half g_zh[(size_t)M_TOK * E_DIM];     // A of GEMM1
__device__ __half g_wh[(size_t)E_DIM * E_DIM];     // B of GEMM1
__device__ __half g_w2h[(size_t)E_DIM * NQ];       // B of GEMM2
__device__ __half g_qh[(size_t)M_TOK * NQ];        // A of GEMM2

// ---------------- PTX helpers (compute_100-safe) -------------------------
__device__ __forceinline__ uint32_t smem_u32(const void* p) {
    uint32_t a;
    asm("{ .reg .u64 t; cvta.to.shared.u64 t, %1; cvt.u32.u64 %0, t; }" : "=r"(a) : "l"(p));
    return a;
}
__device__ __forceinline__ void cp16(uint32_t dst, const void* src) {
    asm volatile("cp.async.cg.shared.global [%0], [%1], 16;" :: "r"(dst), "l"(src));
}
#define CP_COMMIT() asm volatile("cp.async.commit_group;" ::: "memory")
#define CP_WAIT1()  asm volatile("cp.async.wait_group 1;" ::: "memory")
#define CP_WAIT0()  asm volatile("cp.async.wait_group 0;" ::: "memory")

#define LDSM4(r, addr)                                                        \
    asm volatile("ldmatrix.sync.aligned.m8n8.x4.shared.b16 {%0,%1,%2,%3}, [%4];" \
        : "=r"((r)[0]), "=r"((r)[1]), "=r"((r)[2]), "=r"((r)[3]) : "r"(addr))

#define MMA16816(d, a, b)                                                     \
    asm volatile("mma.sync.aligned.m16n8k16.row.col.f32.f16.f16.f32 "         \
        "{%0,%1,%2,%3}, {%4,%5,%6,%7}, {%8,%9}, {%0,%1,%2,%3};"               \
        : "+f"((d)[0]), "+f"((d)[1]), "+f"((d)[2]), "+f"((d)[3])              \
        : "r"((a)[0]), "r"((a)[1]), "r"((a)[2]), "r"((a)[3]),                 \
          "r"((b)[0]), "r"((b)[1]))

// ---------------- fp16 GEMM: C = A*B^T + bias ----------------------------
// A fp16 [M,K] row-major; B fp16 [N,K] row-major.
// CTA 128x128, 4 warps (2x2), warp tile 64x64, BK=64, 2-stage cp.async,
// 2 CTAs/SM.
#define BM 128
#define BN 128
#define BK 64
#define ROWB 144                     // 128 data bytes + 16 pad
#define MAT_B (128 * ROWB)           // bytes per 128x64 fp16 tile (18432)
#define STG   (2 * MAT_B)            // A, B per stage (36864)
#define SM_BIAS (2 * STG)
#define SM_TOT  (SM_BIAS + BN * 4)

__global__ __launch_bounds__(128, 2) void mma_gemm(
    const __half* __restrict__ Ah, const __half* __restrict__ Bh,
    const float* __restrict__ bias, float* __restrict__ Cout, int K) {
    extern __shared__ char smem[];
    const uint32_t sbase = smem_u32(smem);
    float* sbias = (float*)(smem + SM_BIAS);
    const int tid = threadIdx.x, wid = tid >> 5, lane = tid & 31;
    const int m0 = blockIdx.y * BM, n0 = blockIdx.x * BN;
    const int m_off = (wid & 1) * 64;        // 2x2 warp grid, 64x64 each
    const int n_off = (wid >> 1) * 64;

    sbias[tid] = bias[n0 + tid];

    const uint32_t aRow = (uint32_t)(m_off + (lane & 15)) * ROWB + (lane >> 4) * 16;
    const uint32_t bRow = (uint32_t)(n_off + ((lane >> 4) << 3) + (lane & 7)) * ROWB
                        + ((lane >> 3) & 1) * 16;

    float acc[4][8][4] = {};   // [mi][ni][4]

    auto load_stage = [&](int s, int kc0) {
        uint32_t sb = sbase + s * STG;
        #pragma unroll
        for (int i = 0; i < 8; ++i) {
            int c = tid + i * 128;               // 1024 16B-chunks per matrix
            int r = c >> 3, ch = c & 7;          // 128 rows x 8 chunks (128B/row)
            uint32_t d = (uint32_t)r * ROWB + ch * 16;
            size_t goA = (size_t)(m0 + r) * K + kc0 + ch * 8;
            size_t goB = (size_t)(n0 + r) * K + kc0 + ch * 8;
            cp16(sb + d,         Ah + goA);
            cp16(sb + MAT_B + d, Bh + goB);
        }
        CP_COMMIT();
    };

    const int C = K / BK;
    load_stage(0, 0);

    for (int ki = 0; ki < C; ++ki) {
        int cur = ki & 1;
        if (ki + 1 < C) { load_stage(cur ^ 1, (ki + 1) * BK); CP_WAIT1(); }
        else           { CP_WAIT0(); }
        __syncthreads();

        uint32_t base = sbase + cur * STG;
        uint32_t aH = base + aRow;
        uint32_t bH = base + MAT_B + bRow;

        #pragma unroll
        for (int ks = 0; ks < 4; ++ks) {         // four k16 steps per BK=64
            uint32_t ah[4][4], bh[8][2];
            #pragma unroll
            for (int mi = 0; mi < 4; ++mi)
                LDSM4(ah[mi], aH + ks * 32 + mi * 16 * ROWB);
            #pragma unroll
            for (int p = 0; p < 4; ++p) {        // each x4 covers two n8 groups
                uint32_t t[4];
                LDSM4(t, bH + ks * 32 + p * 16 * ROWB);
                bh[2 * p][0] = t[0]; bh[2 * p][1] = t[1];
                bh[2 * p + 1][0] = t[2]; bh[2 * p + 1][1] = t[3];
            }
            #pragma unroll
            for (int mi = 0; mi < 4; ++mi)
                #pragma unroll
                for (int ni = 0; ni < 8; ++ni)
                    MMA16816(acc[mi][ni], ah[mi], bh[ni]);
        }
        __syncthreads();
    }

    // epilogue
    #pragma unroll
    for (int mi = 0; mi < 4; ++mi) {
        int m = m0 + m_off + mi * 16 + (lane >> 2);
        #pragma unroll
        for (int ni = 0; ni < 8; ++ni) {
            int nl = n_off + ni * 8 + 2 * (lane & 3);
            float2 bv = *(float2*)&sbias[nl];
            float* p0 = Cout + (size_t)m * E_DIM + n0 + nl;
            float* p1 = p0 + 8 * E_DIM;
            float2 o0 = {acc[mi][ni][0] + bv.x, acc[mi][ni][1] + bv.y};
            float2 o1 = {acc[mi][ni][2] + bv.x, acc[mi][ni][3] + bv.y};
            *(float2*)p0 = o0;
            *(float2*)p1 = o1;
        }
    }
}

// ---------------- z = cos(x + a0[e%64])*cos(a1[e%64]) -> fp16 ------------
union HPack { __half h[4]; uint2 u; };

__global__ __launch_bounds__(256) void z_half_kernel(const float* __restrict__ x,
                                                     const float* __restrict__ aqp,
                                                     __half* __restrict__ zh) {
    __shared__ float sa0[NQ], sc1[NQ];
    if (threadIdx.x < NQ) {
        sa0[threadIdx.x] = aqp[threadIdx.x * 3 + 0];
        sc1[threadIdx.x] = __cosf(aqp[threadIdx.x * 3 + 1]);
    }
    __syncthreads();
    int i = blockIdx.x * blockDim.x + threadIdx.x;
    int d = (i * 4) & 63;
    float4 v = ((const float4*)x)[i];
    HPack h;
    h.h[0] = __float2half(__cosf(v.x + sa0[d + 0]) * sc1[d + 0]);
    h.h[1] = __float2half(__cosf(v.y + sa0[d + 1]) * sc1[d + 1]);
    h.h[2] = __float2half(__cosf(v.z + sa0[d + 2]) * sc1[d + 2]);
    h.h[3] = __float2half(__cosf(v.w + sa0[d + 3]) * sc1[d + 3]);
    ((uint2*)zh)[i] = h.u;
}

// ---------------- weight -> fp16 ----------------
__global__ __launch_bounds__(256) void w_half_kernel(const float* __restrict__ w,
                                                     __half* __restrict__ h, int n) {
    for (int i = blockIdx.x * blockDim.x + threadIdx.x; i < n; i += gridDim.x * blockDim.x)
        h[i] = __float2half(w[i]);
}

// ---------------- LN1 + q (fp16) ----------------
__global__ __launch_bounds__(256) void ln1_kernel(const float* __restrict__ x,
                                                  const float* __restrict__ attn,
                                                  const float* __restrict__ w,
                                                  const float* __restrict__ b,
                                                  const float* __restrict__ fqp,
                                                  float* __restrict__ x1,
                                                  __half* __restrict__ qh) {
    int row  = blockIdx.x * 8 + (threadIdx.x >> 5);
    int lane = threadIdx.x & 31;
    const float4* px = (const float4*)(x    + (size_t)row * E_DIM);
    const float4* pa = (const float4*)(attn + (size_t)row * E_DIM);
    float4 v[8];
    float s = 0.f, ss = 0.f;
    #pragma unroll
    for (int j = 0; j < 8; ++j) {
        float4 a = px[lane + j * 32];
        float4 t = pa[lane + j * 32];
        float4 u = {a.x + t.x, a.y + t.y, a.z + t.z, a.w + t.w};
        v[j] = u;
        s  += u.x + u.y + u.z + u.w;
        ss += u.x * u.x + u.y * u.y + u.z * u.z + u.w * u.w;
    }
    #pragma unroll
    for (int o = 16; o; o >>= 1) {
        s  += __shfl_xor_sync(0xffffffffu, s, o);
        ss += __shfl_xor_sync(0xffffffffu, ss, o);
    }
    float mu  = s * (1.f / E_DIM);
    float var = ss * (1.f / E_DIM) - mu * mu;
    float rs  = rsqrtf(var + 1e-5f);

    float4* po = (float4*)(x1 + (size_t)row * E_DIM);
    #pragma unroll
    for (int j = 0; j < 8; ++j) {
        int c4 = lane + j * 32;
        float4 wv = ((const float4*)w)[c4];
        float4 bv = ((const float4*)b)[c4];
        float4 u  = v[j];
        float4 o;
        o.x = (u.x - mu) * rs * wv.x + bv.x;
        o.y = (u.y - mu) * rs * wv.y + bv.y;
        o.z = (u.z - mu) * rs * wv.z + bv.z;
        o.w = (u.w - mu) * rs * wv.w + bv.w;
        po[c4] = o;
        if (j == 0 && lane < 16) {
            int k = lane * 4;
            HPack h;
            h.h[0] = __float2half(__cosf(o.x + fqp[(k + 0) * 3]) * __cosf(fqp[(k + 0) * 3 + 1]));
            h.h[1] = __float2half(__cosf(o.y + fqp[(k + 1) * 3]) * __cosf(fqp[(k + 1) * 3 + 1]));
            h.h[2] = __float2half(__cosf(o.z + fqp[(k + 2) * 3]) * __cosf(fqp[(k + 2) * 3 + 1]));
            h.h[3] = __float2half(__cosf(o.w + fqp[(k + 3) * 3]) * __cosf(fqp[(k + 3) * 3 + 1]));
            *(uint2*)(qh + (size_t)row * NQ + k) = h.u;
        }
    }
}

// ---------------- LN2 ----------------
__global__ __launch_bounds__(256) void ln2_kernel(const float* __restrict__ x1,
                                                  const float* __restrict__ ffn,
                                                  const float* __restrict__ w,
                                                  const float* __restrict__ b,
                                                  float* __restrict__ out) {
    int row  = blockIdx.x * 8 + (threadIdx.x >> 5);
    int lane = threadIdx.x & 31;
    const float4* px = (const float4*)(x1  + (size_t)row * E_DIM);
    const float4* pf = (const float4*)(ffn + (size_t)row * E_DIM);
    float4 v[8];
    float s = 0.f, ss = 0.f;
    #pragma unroll
    for (int j = 0; j < 8; ++j) {
        float4 a = px[lane + j * 32];
        float4 t = pf[lane + j * 32];
        float4 u = {a.x + t.x, a.y + t.y, a.z + t.z, a.w + t.w};
        v[j] = u;
        s  += u.x + u.y + u.z + u.w;
        ss += u.x * u.x + u.y * u.y + u.z * u.z + u.w * u.w;
    }
    #pragma unroll
    for (int o = 16; o; o >>= 1) {
        s  += __shfl_xor_sync(0xffffffffu, s, o);
        ss += __shfl_xor_sync(0xffffffffu, ss, o);
    }
    float mu  = s * (1.f / E_DIM);
    float var = ss * (1.f / E_DIM) - mu * mu;
    float rs  = rsqrtf(var + 1e-5f);

    float4* po = (float4*)(out + (size_t)row * E_DIM);
    #pragma unroll
    for (int j = 0; j < 8; ++j) {
        int c4 = lane + j * 32;
        float4 wv = ((const float4*)w)[c4];
        float4 bv = ((const float4*)b)[c4];
        float4 u  = v[j];
        float4 o;
        o.x = (u.x - mu) * rs * wv.x + bv.x;
        o.y = (u.y - mu) * rs * wv.y + bv.y;
        o.z = (u.z - mu) * rs * wv.z + bv.z;
        o.w = (u.w - mu) * rs * wv.w + bv.w;
        po[c4] = o;
    }
}

// ---------------- launcher ----------------
extern "C" void kernel_launch(void* const* d_in, const int* in_sizes, int n_in,
                              void* d_out, int out_size) {
    const float* x   = (const float*)d_in[0];
    const float* aqp = (const float*)d_in[1];
    const float* opw = (const float*)d_in[2];
    const float* opb = (const float*)d_in[3];
    const float* fqp = (const float*)d_in[4];
    const float* flw = (const float*)d_in[5];
    const float* flb = (const float*)d_in[6];
    const float* n1w = (const float*)d_in[7];
    const float* n1b = (const float*)d_in[8];
    const float* n2w = (const float*)d_in[9];
    const float* n2b = (const float*)d_in[10];
    float* out = (float*)d_out;

    float *attn, *x1;
    __half *zh, *wh, *w2h, *qh;
    cudaGetSymbolAddress((void**)&attn, g_attn);
    cudaGetSymbolAddress((void**)&x1,   g_x1);
    cudaGetSymbolAddress((void**)&zh,   g_zh);
    cudaGetSymbolAddress((void**)&wh,   g_wh);
    cudaGetSymbolAddress((void**)&w2h,  g_w2h);
    cudaGetSymbolAddress((void**)&qh,   g_qh);

    cudaFuncSetAttribute(mma_gemm, cudaFuncAttributeMaxDynamicSharedMemorySize, SM_TOT);

    // 1) z -> fp16
    z_half_kernel<<<(M_TOK * E_DIM / 4) / 256, 256>>>(x, aqp, zh);
    // 2) weights -> fp16
    w_half_kernel<<<2048, 256>>>(opw, wh, E_DIM * E_DIM);
    w_half_kernel<<<256, 256>>>(flw, w2h, E_DIM * NQ);
    // 3) attn = z @ opw^T + opb
    dim3 g1(E_DIM / BN, M_TOK / BM);
    mma_gemm<<<g1, 128, SM_TOT>>>(zh, wh, opb, attn, E_DIM);
    // 4) x1 = LN1(x + attn); q -> fp16
    ln1_kernel<<<M_TOK / 8, 256>>>(x, attn, n1w, n1b, fqp, x1, qh);
    // 5) ffn = q @ flw^T + flb   (K = 64, single iteration)
    mma_gemm<<<g1, 128, SM_TOT>>>(qh, w2h, flb, attn, NQ);
    // 6) out = LN2(x1 + ffn)
    ln2_kernel<<<M_TOK / 8, 256>>>(x1, attn, n2w, n2b, out);
}

// round 9
// speedup vs baseline: 2.1107x; 1.0423x over previous
#include <cuda_runtime.h>
#include <cuda_fp16.h>
#include <cstdint>

#define M_TOK 16384   // B*S
#define E_DIM 1024
#define NQ    64

// ---------------- scratch (__device__ globals; no allocs) ----------------
__device__ __half g_attn[(size_t)M_TOK * E_DIM];   // fp16 gemm outputs (attn, then ffn)
__device__ __half g_x1h[(size_t)M_TOK * E_DIM];    // fp16 x1
__device__ __half g_zh[(size_t)M_TOK * E_DIM];     // A of GEMM1
__device__ __half g_wh[(size_t)E_DIM * E_DIM];     // B of GEMM1
__device__ __half g_w2h[(size_t)E_DIM * NQ];       // B of GEMM2
__device__ __half g_qh[(size_t)M_TOK * NQ];        // A of GEMM2

// ---------------- PTX helpers (compute_100-safe) -------------------------
__device__ __forceinline__ uint32_t smem_u32(const void* p) {
    uint32_t a;
    asm("{ .reg .u64 t; cvta.to.shared.u64 t, %1; cvt.u32.u64 %0, t; }" : "=r"(a) : "l"(p));
    return a;
}
__device__ __forceinline__ void cp16(uint32_t dst, const void* src) {
    asm volatile("cp.async.cg.shared.global [%0], [%1], 16;" :: "r"(dst), "l"(src));
}
#define CP_COMMIT() asm volatile("cp.async.commit_group;" ::: "memory")
#define CP_WAIT1()  asm volatile("cp.async.wait_group 1;" ::: "memory")
#define CP_WAIT0()  asm volatile("cp.async.wait_group 0;" ::: "memory")

#define LDSM4(r, addr)                                                        \
    asm volatile("ldmatrix.sync.aligned.m8n8.x4.shared.b16 {%0,%1,%2,%3}, [%4];" \
        : "=r"((r)[0]), "=r"((r)[1]), "=r"((r)[2]), "=r"((r)[3]) : "r"(addr))

#define MMA16816(d, a, b)                                                     \
    asm volatile("mma.sync.aligned.m16n8k16.row.col.f32.f16.f16.f32 "         \
        "{%0,%1,%2,%3}, {%4,%5,%6,%7}, {%8,%9}, {%0,%1,%2,%3};"               \
        : "+f"((d)[0]), "+f"((d)[1]), "+f"((d)[2]), "+f"((d)[3])              \
        : "r"((a)[0]), "r"((a)[1]), "r"((a)[2]), "r"((a)[3]),                 \
          "r"((b)[0]), "r"((b)[1]))

// ---------------- persistent fp16 GEMM: C = A*B^T + bias (fp16 out) ------
// CTA 128x128 tiles, 4 warps (2x2), warp tile 64x64, BK=64, 2-stage.
// Persistent: grid = 2*SMs, tile t = t0 + w*grid; flat stage parity across
// tiles; next tile's stage-0 load overlaps this tile's epilogue.
#define BM 128
#define BN 128
#define BK 64
#define ROWB 144                     // 128 data bytes + 16 pad
#define MAT_B (128 * ROWB)
#define STG   (2 * MAT_B)
#define SM_TOT (2 * STG)
#define NT_TILES 8                   // N tiles per row band (E_DIM / BN)

__global__ __launch_bounds__(128, 2) void mma_gemm(
    const __half* __restrict__ Ah, const __half* __restrict__ Bh,
    const float* __restrict__ bias, __half* __restrict__ Cout,
    int K, int total_tiles) {
    extern __shared__ char smem[];
    const uint32_t sbase = smem_u32(smem);
    const int tid = threadIdx.x, wid = tid >> 5, lane = tid & 31;
    const int m_off = (wid & 1) * 64;
    const int n_off = (wid >> 1) * 64;
    const int grid = gridDim.x;
    const int t0 = blockIdx.x;
    const int nt = (total_tiles - t0 + grid - 1) / grid;
    const int C = K / BK;

    const uint32_t aRow = (uint32_t)(m_off + (lane & 15)) * ROWB + (lane >> 4) * 16;
    const uint32_t bRow = (uint32_t)(n_off + ((lane >> 4) << 3) + (lane & 7)) * ROWB
                        + ((lane >> 3) & 1) * 16;

    auto load_stage = [&](int s, int m0, int n0, int kc0) {
        uint32_t sb = sbase + s * STG;
        #pragma unroll
        for (int i = 0; i < 8; ++i) {
            int c = tid + i * 128;               // 1024 16B-chunks per matrix
            int r = c >> 3, ch = c & 7;
            uint32_t d = (uint32_t)r * ROWB + ch * 16;
            cp16(sb + d,         Ah + (size_t)(m0 + r) * K + kc0 + ch * 8);
            cp16(sb + MAT_B + d, Bh + (size_t)(n0 + r) * K + kc0 + ch * 8);
        }
        CP_COMMIT();
    };

    {   // prologue: first tile, first chunk
        int t = t0;
        load_stage(0, (t >> 3) * BM, (t & (NT_TILES - 1)) * BN, 0);
    }
    int par = 0;

    for (int ti = 0; ti < nt; ++ti) {
        int t  = t0 + ti * grid;
        int m0 = (t >> 3) * BM, n0 = (t & (NT_TILES - 1)) * BN;

        float acc[4][8][4];
        #pragma unroll
        for (int a = 0; a < 4; ++a)
            #pragma unroll
            for (int b2 = 0; b2 < 8; ++b2)
                #pragma unroll
                for (int c2 = 0; c2 < 4; ++c2) acc[a][b2][c2] = 0.f;

        for (int ki = 0; ki < C; ++ki) {
            bool last = (ki == C - 1) && (ti == nt - 1);
            if (!last) {
                int nti = ti, nki = ki + 1;
                if (nki == C) { nki = 0; nti = ti + 1; }
                int t2 = t0 + nti * grid;
                load_stage(par ^ 1, (t2 >> 3) * BM, (t2 & (NT_TILES - 1)) * BN, nki * BK);
                CP_WAIT1();
            } else {
                CP_WAIT0();
            }
            __syncthreads();

            uint32_t base = sbase + par * STG;
            uint32_t aH = base + aRow;
            uint32_t bH = base + MAT_B + bRow;

            #pragma unroll
            for (int ks = 0; ks < 4; ++ks) {         // four k16 steps per BK=64
                uint32_t ah[4][4], bh[8][2];
                #pragma unroll
                for (int mi = 0; mi < 4; ++mi)
                    LDSM4(ah[mi], aH + ks * 32 + mi * 16 * ROWB);
                #pragma unroll
                for (int p = 0; p < 4; ++p) {
                    uint32_t tt[4];
                    LDSM4(tt, bH + ks * 32 + p * 16 * ROWB);
                    bh[2 * p][0] = tt[0]; bh[2 * p][1] = tt[1];
                    bh[2 * p + 1][0] = tt[2]; bh[2 * p + 1][1] = tt[3];
                }
                #pragma unroll
                for (int mi = 0; mi < 4; ++mi)
                    #pragma unroll
                    for (int ni = 0; ni < 8; ++ni)
                        MMA16816(acc[mi][ni], ah[mi], bh[ni]);
            }
            par ^= 1;
            __syncthreads();
        }

        // epilogue (fp16 store); next tile's stage-0 cp.async already in flight
        #pragma unroll
        for (int mi = 0; mi < 4; ++mi) {
            int m = m0 + m_off + mi * 16 + (lane >> 2);
            #pragma unroll
            for (int ni = 0; ni < 8; ++ni) {
                int nl = n_off + ni * 8 + 2 * (lane & 3);
                float2 bv = *(const float2*)&bias[n0 + nl];
                __half* p0 = Cout + (size_t)m * E_DIM + n0 + nl;
                __half* p1 = p0 + 8 * E_DIM;
                *(__half2*)p0 = __floats2half2_rn(acc[mi][ni][0] + bv.x, acc[mi][ni][1] + bv.y);
                *(__half2*)p1 = __floats2half2_rn(acc[mi][ni][2] + bv.x, acc[mi][ni][3] + bv.y);
            }
        }
    }
}

// ---------------- z = cos(x + a0[e%64])*cos(a1[e%64]) -> fp16 ------------
union HPack { __half h[4]; uint2 u; };

__global__ __launch_bounds__(256) void z_half_kernel(const float* __restrict__ x,
                                                     const float* __restrict__ aqp,
                                                     __half* __restrict__ zh) {
    __shared__ float sa0[NQ], sc1[NQ];
    if (threadIdx.x < NQ) {
        sa0[threadIdx.x] = aqp[threadIdx.x * 3 + 0];
        sc1[threadIdx.x] = __cosf(aqp[threadIdx.x * 3 + 1]);
    }
    __syncthreads();
    int i = blockIdx.x * blockDim.x + threadIdx.x;
    int d = (i * 4) & 63;
    float4 v = ((const float4*)x)[i];
    HPack h;
    h.h[0] = __float2half(__cosf(v.x + sa0[d + 0]) * sc1[d + 0]);
    h.h[1] = __float2half(__cosf(v.y + sa0[d + 1]) * sc1[d + 1]);
    h.h[2] = __float2half(__cosf(v.z + sa0[d + 2]) * sc1[d + 2]);
    h.h[3] = __float2half(__cosf(v.w + sa0[d + 3]) * sc1[d + 3]);
    ((uint2*)zh)[i] = h.u;
}

// ---------------- weight -> fp16 ----------------
__global__ __launch_bounds__(256) void w_half_kernel(const float* __restrict__ w,
                                                     __half* __restrict__ h, int n) {
    for (int i = blockIdx.x * blockDim.x + threadIdx.x; i < n; i += gridDim.x * blockDim.x)
        h[i] = __float2half(w[i]);
}

// ---------------- LN1: x(fp32) + attn(fp16) -> x1(fp16), q(fp16) ---------
__global__ __launch_bounds__(256) void ln1_kernel(const float* __restrict__ x,
                                                  const __half* __restrict__ attn,
                                                  const float* __restrict__ w,
                                                  const float* __restrict__ b,
                                                  const float* __restrict__ fqp,
                                                  __half* __restrict__ x1,
                                                  __half* __restrict__ qh) {
    int row  = blockIdx.x * 8 + (threadIdx.x >> 5);
    int lane = threadIdx.x & 31;
    const float4* px = (const float4*)(x    + (size_t)row * E_DIM);
    const uint2*  pa = (const uint2*)(attn + (size_t)row * E_DIM);
    float4 v[8];
    float s = 0.f, ss = 0.f;
    #pragma unroll
    for (int j = 0; j < 8; ++j) {
        float4 a = px[lane + j * 32];
        uint2 t = pa[lane + j * 32];
        float2 f0 = __half22float2(*(__half2*)&t.x);
        float2 f1 = __half22float2(*(__half2*)&t.y);
        float4 u = {a.x + f0.x, a.y + f0.y, a.z + f1.x, a.w + f1.y};
        v[j] = u;
        s  += u.x + u.y + u.z + u.w;
        ss += u.x * u.x + u.y * u.y + u.z * u.z + u.w * u.w;
    }
    #pragma unroll
    for (int o = 16; o; o >>= 1) {
        s  += __shfl_xor_sync(0xffffffffu, s, o);
        ss += __shfl_xor_sync(0xffffffffu, ss, o);
    }
    float mu  = s * (1.f / E_DIM);
    float var = ss * (1.f / E_DIM) - mu * mu;
    float rs  = rsqrtf(var + 1e-5f);

    uint2* po = (uint2*)(x1 + (size_t)row * E_DIM);
    #pragma unroll
    for (int j = 0; j < 8; ++j) {
        int c4 = lane + j * 32;
        float4 wv = ((const float4*)w)[c4];
        float4 bv = ((const float4*)b)[c4];
        float4 u  = v[j];
        float4 o;
        o.x = (u.x - mu) * rs * wv.x + bv.x;
        o.y = (u.y - mu) * rs * wv.y + bv.y;
        o.z = (u.z - mu) * rs * wv.z + bv.z;
        o.w = (u.w - mu) * rs * wv.w + bv.w;
        HPack hp;
        hp.h[0] = __float2half(o.x); hp.h[1] = __float2half(o.y);
        hp.h[2] = __float2half(o.z); hp.h[3] = __float2half(o.w);
        po[c4] = hp.u;
        if (j == 0 && lane < 16) {
            int k = lane * 4;
            HPack hq;
            hq.h[0] = __float2half(__cosf(o.x + fqp[(k + 0) * 3]) * __cosf(fqp[(k + 0) * 3 + 1]));
            hq.h[1] = __float2half(__cosf(o.y + fqp[(k + 1) * 3]) * __cosf(fqp[(k + 1) * 3 + 1]));
            hq.h[2] = __float2half(__cosf(o.z + fqp[(k + 2) * 3]) * __cosf(fqp[(k + 2) * 3 + 1]));
            hq.h[3] = __float2half(__cosf(o.w + fqp[(k + 3) * 3]) * __cosf(fqp[(k + 3) * 3 + 1]));
            *(uint2*)(qh + (size_t)row * NQ + k) = hq.u;
        }
    }
}

// ---------------- LN2: x1(fp16) + ffn(fp16) -> out(fp32) ----------------
__global__ __launch_bounds__(256) void ln2_kernel(const __half* __restrict__ x1,
                                                  const __half* __restrict__ ffn,
                                                  const float* __restrict__ w,
                                                  const float* __restrict__ b,
                                                  float* __restrict__ out) {
    int row  = blockIdx.x * 8 + (threadIdx.x >> 5);
    int lane = threadIdx.x & 31;
    const uint2* px = (const uint2*)(x1  + (size_t)row * E_DIM);
    const uint2* pf = (const uint2*)(ffn + (size_t)row * E_DIM);
    float4 v[8];
    float s = 0.f, ss = 0.f;
    #pragma unroll
    for (int j = 0; j < 8; ++j) {
        uint2 ta = px[lane + j * 32];
        uint2 tf = pf[lane + j * 32];
        float2 a0 = __half22float2(*(__half2*)&ta.x);
        float2 a1 = __half22float2(*(__half2*)&ta.y);
        float2 f0 = __half22float2(*(__half2*)&tf.x);
        float2 f1 = __half22float2(*(__half2*)&tf.y);
        float4 u = {a0.x + f0.x, a0.y + f0.y, a1.x + f1.x, a1.y + f1.y};
        v[j] = u;
        s  += u.x + u.y + u.z + u.w;
        ss += u.x * u.x + u.y * u.y + u.z * u.z + u.w * u.w;
    }
    #pragma unroll
    for (int o = 16; o; o >>= 1) {
        s  += __shfl_xor_sync(0xffffffffu, s, o);
        ss += __shfl_xor_sync(0xffffffffu, ss, o);
    }
    float mu  = s * (1.f / E_DIM);
    float var = ss * (1.f / E_DIM) - mu * mu;
    float rs  = rsqrtf(var + 1e-5f);

    float4* po = (float4*)(out + (size_t)row * E_DIM);
    #pragma unroll
    for (int j = 0; j < 8; ++j) {
        int c4 = lane + j * 32;
        float4 wv = ((const float4*)w)[c4];
        float4 bv = ((const float4*)b)[c4];
        float4 u  = v[j];
        float4 o;
        o.x = (u.x - mu) * rs * wv.x + bv.x;
        o.y = (u.y - mu) * rs * wv.y + bv.y;
        o.z = (u.z - mu) * rs * wv.z + bv.z;
        o.w = (u.w - mu) * rs * wv.w + bv.w;
        po[c4] = o;
    }
}

// ---------------- launcher ----------------
extern "C" void kernel_launch(void* const* d_in, const int* in_sizes, int n_in,
                              void* d_out, int out_size) {
    const float* x   = (const float*)d_in[0];
    const float* aqp = (const float*)d_in[1];
    const float* opw = (const float*)d_in[2];
    const float* opb = (const float*)d_in[3];
    const float* fqp = (const float*)d_in[4];
    const float* flw = (const float*)d_in[5];
    const float* flb = (const float*)d_in[6];
    const float* n1w = (const float*)d_in[7];
    const float* n1b = (const float*)d_in[8];
    const float* n2w = (const float*)d_in[9];
    const float* n2b = (const float*)d_in[10];
    float* out = (float*)d_out;

    __half *attnh, *x1h, *zh, *wh, *w2h, *qh;
    cudaGetSymbolAddress((void**)&attnh, g_attn);
    cudaGetSymbolAddress((void**)&x1h,   g_x1h);
    cudaGetSymbolAddress((void**)&zh,    g_zh);
    cudaGetSymbolAddress((void**)&wh,    g_wh);
    cudaGetSymbolAddress((void**)&w2h,   g_w2h);
    cudaGetSymbolAddress((void**)&qh,    g_qh);

    static int nsm = 0;
    if (nsm == 0) {
        cudaDeviceGetAttribute(&nsm, cudaDevAttrMultiProcessorCount, 0);
        cudaFuncSetAttribute(mma_gemm, cudaFuncAttributeMaxDynamicSharedMemorySize, SM_TOT);
    }
    int gp = nsm * 2;                    // persistent: 2 CTAs/SM, all resident
    const int total_tiles = (M_TOK / BM) * (E_DIM / BN);   // 1024
    if (gp > total_tiles) gp = total_tiles;

    // 1) z -> fp16
    z_half_kernel<<<(M_TOK * E_DIM / 4) / 256, 256>>>(x, aqp, zh);
    // 2) weights -> fp16
    w_half_kernel<<<2048, 256>>>(opw, wh, E_DIM * E_DIM);
    w_half_kernel<<<256, 256>>>(flw, w2h, E_DIM * NQ);
    // 3) attn = z @ opw^T + opb   (persistent, fp16 out)
    mma_gemm<<<gp, 128, SM_TOT>>>(zh, wh, opb, attnh, E_DIM, total_tiles);
    // 4) x1 = LN1(x + attn) -> fp16; q -> fp16
    ln1_kernel<<<M_TOK / 8, 256>>>(x, attnh, n1w, n1b, fqp, x1h, qh);
    // 5) ffn = q @ flw^T + flb   (K = 64, persistent)
    mma_gemm<<<gp, 128, SM_TOT>>>(qh, w2h, flb, attnh, NQ, total_tiles);
    // 6) out = LN2(x1 + ffn)
    ln2_kernel<<<M_TOK / 8, 256>>>(x1h, attnh, n2w, n2b, out);
}

// round 10
// speedup vs baseline: 2.2475x; 1.0648x over previous
#include <cuda_runtime.h>
#include <cuda_fp16.h>
#include <cstdint>

#define M_TOK 16384   // B*S
#define E_DIM 1024
#define NQ    64

// ---------------- scratch (__device__ globals; no allocs) ----------------
__device__ __half g_attn[(size_t)M_TOK * E_DIM];   // fp16 gemm outputs (attn, then ffn)
__device__ __half g_x1h[(size_t)M_TOK * E_DIM];    // fp16 x1
__device__ __half g_zh[(size_t)M_TOK * E_DIM];     // A of GEMM1
__device__ __half g_wh[(size_t)E_DIM * E_DIM];     // B of GEMM1
__device__ __half g_w2h[(size_t)E_DIM * NQ];       // B of GEMM2
__device__ __half g_qh[(size_t)M_TOK * NQ];        // A of GEMM2

// ---------------- PTX helpers (compute_100-safe) -------------------------
__device__ __forceinline__ uint32_t smem_u32(const void* p) {
    uint32_t a;
    asm("{ .reg .u64 t; cvta.to.shared.u64 t, %1; cvt.u32.u64 %0, t; }" : "=r"(a) : "l"(p));
    return a;
}
__device__ __forceinline__ void cp16(uint32_t dst, const void* src) {
    asm volatile("cp.async.cg.shared.global [%0], [%1], 16;" :: "r"(dst), "l"(src));
}
#define CP_COMMIT() asm volatile("cp.async.commit_group;" ::: "memory")
#define CP_WAIT1()  asm volatile("cp.async.wait_group 1;" ::: "memory")
#define CP_WAIT0()  asm volatile("cp.async.wait_group 0;" ::: "memory")

#define LDSM4(r, addr)                                                        \
    asm volatile("ldmatrix.sync.aligned.m8n8.x4.shared.b16 {%0,%1,%2,%3}, [%4];" \
        : "=r"((r)[0]), "=r"((r)[1]), "=r"((r)[2]), "=r"((r)[3]) : "r"(addr))

#define MMA16816(d, a, b)                                                     \
    asm volatile("mma.sync.aligned.m16n8k16.row.col.f32.f16.f16.f32 "         \
        "{%0,%1,%2,%3}, {%4,%5,%6,%7}, {%8,%9}, {%0,%1,%2,%3};"               \
        : "+f"((d)[0]), "+f"((d)[1]), "+f"((d)[2]), "+f"((d)[3])              \
        : "r"((a)[0]), "r"((a)[1]), "r"((a)[2]), "r"((a)[3]),                 \
          "r"((b)[0]), "r"((b)[1]))

// ---------------- fp16 GEMM: C = A*B^T + bias (fp16 out) -----------------
// A fp16 [M,K] row-major; B fp16 [N,K] row-major.
// CTA 128x128, 4 warps (2x2), warp tile 64x64, BK=64, 2-stage cp.async,
// grid = all tiles (1024), 2 CTAs/SM.  [r8 structure, empirically best]
#define BM 128
#define BN 128
#define BK 64
#define ROWB 144                     // 128 data bytes + 16 pad
#define MAT_B (128 * ROWB)           // bytes per 128x64 fp16 tile (18432)
#define STG   (2 * MAT_B)            // A, B per stage (36864)
#define SM_BIAS (2 * STG)
#define SM_TOT  (SM_BIAS + BN * 4)

__global__ __launch_bounds__(128, 2) void mma_gemm(
    const __half* __restrict__ Ah, const __half* __restrict__ Bh,
    const float* __restrict__ bias, __half* __restrict__ Cout, int K) {
    extern __shared__ char smem[];
    const uint32_t sbase = smem_u32(smem);
    float* sbias = (float*)(smem + SM_BIAS);
    const int tid = threadIdx.x, wid = tid >> 5, lane = tid & 31;
    const int m0 = blockIdx.y * BM, n0 = blockIdx.x * BN;
    const int m_off = (wid & 1) * 64;        // 2x2 warp grid, 64x64 each
    const int n_off = (wid >> 1) * 64;

    sbias[tid] = bias[n0 + tid];

    const uint32_t aRow = (uint32_t)(m_off + (lane & 15)) * ROWB + (lane >> 4) * 16;
    const uint32_t bRow = (uint32_t)(n_off + ((lane >> 4) << 3) + (lane & 7)) * ROWB
                        + ((lane >> 3) & 1) * 16;

    float acc[4][8][4] = {};   // [mi][ni][4]

    auto load_stage = [&](int s, int kc0) {
        uint32_t sb = sbase + s * STG;
        #pragma unroll
        for (int i = 0; i < 8; ++i) {
            int c = tid + i * 128;               // 1024 16B-chunks per matrix
            int r = c >> 3, ch = c & 7;          // 128 rows x 8 chunks (128B/row)
            uint32_t d = (uint32_t)r * ROWB + ch * 16;
            size_t goA = (size_t)(m0 + r) * K + kc0 + ch * 8;
            size_t goB = (size_t)(n0 + r) * K + kc0 + ch * 8;
            cp16(sb + d,         Ah + goA);
            cp16(sb + MAT_B + d, Bh + goB);
        }
        CP_COMMIT();
    };

    const int C = K / BK;
    load_stage(0, 0);

    for (int ki = 0; ki < C; ++ki) {
        int cur = ki & 1;
        if (ki + 1 < C) { load_stage(cur ^ 1, (ki + 1) * BK); CP_WAIT1(); }
        else           { CP_WAIT0(); }
        __syncthreads();

        uint32_t base = sbase + cur * STG;
        uint32_t aH = base + aRow;
        uint32_t bH = base + MAT_B + bRow;

        #pragma unroll
        for (int ks = 0; ks < 4; ++ks) {         // four k16 steps per BK=64
            uint32_t ah[4][4], bh[8][2];
            #pragma unroll
            for (int mi = 0; mi < 4; ++mi)
                LDSM4(ah[mi], aH + ks * 32 + mi * 16 * ROWB);
            #pragma unroll
            for (int p = 0; p < 4; ++p) {        // each x4 covers two n8 groups
                uint32_t t[4];
                LDSM4(t, bH + ks * 32 + p * 16 * ROWB);
                bh[2 * p][0] = t[0]; bh[2 * p][1] = t[1];
                bh[2 * p + 1][0] = t[2]; bh[2 * p + 1][1] = t[3];
            }
            #pragma unroll
            for (int mi = 0; mi < 4; ++mi)
                #pragma unroll
                for (int ni = 0; ni < 8; ++ni)
                    MMA16816(acc[mi][ni], ah[mi], bh[ni]);
        }
        __syncthreads();
    }

    // epilogue: fp16 stores (half the bytes of r8)
    #pragma unroll
    for (int mi = 0; mi < 4; ++mi) {
        int m = m0 + m_off + mi * 16 + (lane >> 2);
        #pragma unroll
        for (int ni = 0; ni < 8; ++ni) {
            int nl = n_off + ni * 8 + 2 * (lane & 3);
            float2 bv = *(float2*)&sbias[nl];
            __half* p0 = Cout + (size_t)m * E_DIM + n0 + nl;
            __half* p1 = p0 + 8 * E_DIM;
            *(__half2*)p0 = __floats2half2_rn(acc[mi][ni][0] + bv.x, acc[mi][ni][1] + bv.y);
            *(__half2*)p1 = __floats2half2_rn(acc[mi][ni][2] + bv.x, acc[mi][ni][3] + bv.y);
        }
    }
}

// ---------------- z = cos(x + a0[e%64])*cos(a1[e%64]) -> fp16 ------------
union HPack { __half h[4]; uint2 u; };

__global__ __launch_bounds__(256) void z_half_kernel(const float* __restrict__ x,
                                                     const float* __restrict__ aqp,
                                                     __half* __restrict__ zh) {
    __shared__ float sa0[NQ], sc1[NQ];
    if (threadIdx.x < NQ) {
        sa0[threadIdx.x] = aqp[threadIdx.x * 3 + 0];
        sc1[threadIdx.x] = __cosf(aqp[threadIdx.x * 3 + 1]);
    }
    __syncthreads();
    int i = blockIdx.x * blockDim.x + threadIdx.x;
    int d = (i * 4) & 63;
    float4 v = ((const float4*)x)[i];
    HPack h;
    h.h[0] = __float2half(__cosf(v.x + sa0[d + 0]) * sc1[d + 0]);
    h.h[1] = __float2half(__cosf(v.y + sa0[d + 1]) * sc1[d + 1]);
    h.h[2] = __float2half(__cosf(v.z + sa0[d + 2]) * sc1[d + 2]);
    h.h[3] = __float2half(__cosf(v.w + sa0[d + 3]) * sc1[d + 3]);
    ((uint2*)zh)[i] = h.u;
}

// ---------------- weight -> fp16 ----------------
__global__ __launch_bounds__(256) void w_half_kernel(const float* __restrict__ w,
                                                     __half* __restrict__ h, int n) {
    for (int i = blockIdx.x * blockDim.x + threadIdx.x; i < n; i += gridDim.x * blockDim.x)
        h[i] = __float2half(w[i]);
}

// ---------------- LN1: x(fp32) + attn(fp16) -> x1(fp16), q(fp16) ---------
__global__ __launch_bounds__(256) void ln1_kernel(const float* __restrict__ x,
                                                  const __half* __restrict__ attn,
                                                  const float* __restrict__ w,
                                                  const float* __restrict__ b,
                                                  const float* __restrict__ fqp,
                                                  __half* __restrict__ x1,
                                                  __half* __restrict__ qh) {
    int row  = blockIdx.x * 8 + (threadIdx.x >> 5);
    int lane = threadIdx.x & 31;
    const float4* px = (const float4*)(x    + (size_t)row * E_DIM);
    const uint2*  pa = (const uint2*)(attn + (size_t)row * E_DIM);
    float4 v[8];
    float s = 0.f, ss = 0.f;
    #pragma unroll
    for (int j = 0; j < 8; ++j) {
        float4 a = px[lane + j * 32];
        uint2 t = pa[lane + j * 32];
        float2 f0 = __half22float2(*(__half2*)&t.x);
        float2 f1 = __half22float2(*(__half2*)&t.y);
        float4 u = {a.x + f0.x, a.y + f0.y, a.z + f1.x, a.w + f1.y};
        v[j] = u;
        s  += u.x + u.y + u.z + u.w;
        ss += u.x * u.x + u.y * u.y + u.z * u.z + u.w * u.w;
    }
    #pragma unroll
    for (int o = 16; o; o >>= 1) {
        s  += __shfl_xor_sync(0xffffffffu, s, o);
        ss += __shfl_xor_sync(0xffffffffu, ss, o);
    }
    float mu  = s * (1.f / E_DIM);
    float var = ss * (1.f / E_DIM) - mu * mu;
    float rs  = rsqrtf(var + 1e-5f);

    uint2* po = (uint2*)(x1 + (size_t)row * E_DIM);
    #pragma unroll
    for (int j = 0; j < 8; ++j) {
        int c4 = lane + j * 32;
        float4 wv = ((const float4*)w)[c4];
        float4 bv = ((const float4*)b)[c4];
        float4 u  = v[j];
        float4 o;
        o.x = (u.x - mu) * rs * wv.x + bv.x;
        o.y = (u.y - mu) * rs * wv.y + bv.y;
        o.z = (u.z - mu) * rs * wv.z + bv.z;
        o.w = (u.w - mu) * rs * wv.w + bv.w;
        HPack hp;
        hp.h[0] = __float2half(o.x); hp.h[1] = __float2half(o.y);
        hp.h[2] = __float2half(o.z); hp.h[3] = __float2half(o.w);
        po[c4] = hp.u;
        if (j == 0 && lane < 16) {
            int k = lane * 4;
            HPack hq;
            hq.h[0] = __float2half(__cosf(o.x + fqp[(k + 0) * 3]) * __cosf(fqp[(k + 0) * 3 + 1]));
            hq.h[1] = __float2half(__cosf(o.y + fqp[(k + 1) * 3]) * __cosf(fqp[(k + 1) * 3 + 1]));
            hq.h[2] = __float2half(__cosf(o.z + fqp[(k + 2) * 3]) * __cosf(fqp[(k + 2) * 3 + 1]));
            hq.h[3] = __float2half(__cosf(o.w + fqp[(k + 3) * 3]) * __cosf(fqp[(k + 3) * 3 + 1]));
            *(uint2*)(qh + (size_t)row * NQ + k) = hq.u;
        }
    }
}

// ---------------- LN2: x1(fp16) + ffn(fp16) -> out(fp32) ----------------
__global__ __launch_bounds__(256) void ln2_kernel(const __half* __restrict__ x1,
                                                  const __half* __restrict__ ffn,
                                                  const float* __restrict__ w,
                                                  const float* __restrict__ b,
                                                  float* __restrict__ out) {
    int row  = blockIdx.x * 8 + (threadIdx.x >> 5);
    int lane = threadIdx.x & 31;
    const uint2* px = (const uint2*)(x1  + (size_t)row * E_DIM);
    const uint2* pf = (const uint2*)(ffn + (size_t)row * E_DIM);
    float4 v[8];
    float s = 0.f, ss = 0.f;
    #pragma unroll
    for (int j = 0; j < 8; ++j) {
        uint2 ta = px[lane + j * 32];
        uint2 tf = pf[lane + j * 32];
        float2 a0 = __half22float2(*(__half2*)&ta.x);
        float2 a1 = __half22float2(*(__half2*)&ta.y);
        float2 f0 = __half22float2(*(__half2*)&tf.x);
        float2 f1 = __half22float2(*(__half2*)&tf.y);
        float4 u = {a0.x + f0.x, a0.y + f0.y, a1.x + f1.x, a1.y + f1.y};
        v[j] = u;
        s  += u.x + u.y + u.z + u.w;
        ss += u.x * u.x + u.y * u.y + u.z * u.z + u.w * u.w;
    }
    #pragma unroll
    for (int o = 16; o; o >>= 1) {
        s  += __shfl_xor_sync(0xffffffffu, s, o);
        ss += __shfl_xor_sync(0xffffffffu, ss, o);
    }
    float mu  = s * (1.f / E_DIM);
    float var = ss * (1.f / E_DIM) - mu * mu;
    float rs  = rsqrtf(var + 1e-5f);

    float4* po = (float4*)(out + (size_t)row * E_DIM);
    #pragma unroll
    for (int j = 0; j < 8; ++j) {
        int c4 = lane + j * 32;
        float4 wv = ((const float4*)w)[c4];
        float4 bv = ((const float4*)b)[c4];
        float4 u  = v[j];
        float4 o;
        o.x = (u.x - mu) * rs * wv.x + bv.x;
        o.y = (u.y - mu) * rs * wv.y + bv.y;
        o.z = (u.z - mu) * rs * wv.z + bv.z;
        o.w = (u.w - mu) * rs * wv.w + bv.w;
        po[c4] = o;
    }
}

// ---------------- launcher ----------------
extern "C" void kernel_launch(void* const* d_in, const int* in_sizes, int n_in,
                              void* d_out, int out_size) {
    const float* x   = (const float*)d_in[0];
    const float* aqp = (const float*)d_in[1];
    const float* opw = (const float*)d_in[2];
    const float* opb = (const float*)d_in[3];
    const float* fqp = (const float*)d_in[4];
    const float* flw = (const float*)d_in[5];
    const float* flb = (const float*)d_in[6];
    const float* n1w = (const float*)d_in[7];
    const float* n1b = (const float*)d_in[8];
    const float* n2w = (const float*)d_in[9];
    const float* n2b = (const float*)d_in[10];
    float* out = (float*)d_out;

    __half *attnh, *x1h, *zh, *wh, *w2h, *qh;
    cudaGetSymbolAddress((void**)&attnh, g_attn);
    cudaGetSymbolAddress((void**)&x1h,   g_x1h);
    cudaGetSymbolAddress((void**)&zh,    g_zh);
    cudaGetSymbolAddress((void**)&wh,    g_wh);
    cudaGetSymbolAddress((void**)&w2h,   g_w2h);
    cudaGetSymbolAddress((void**)&qh,    g_qh);

    cudaFuncSetAttribute(mma_gemm, cudaFuncAttributeMaxDynamicSharedMemorySize, SM_TOT);

    // 1) z -> fp16
    z_half_kernel<<<(M_TOK * E_DIM / 4) / 256, 256>>>(x, aqp, zh);
    // 2) weights -> fp16
    w_half_kernel<<<2048, 256>>>(opw, wh, E_DIM * E_DIM);
    w_half_kernel<<<256, 256>>>(flw, w2h, E_DIM * NQ);
    // 3) attn = z @ opw^T + opb   (fp16 out)
    dim3 g1(E_DIM / BN, M_TOK / BM);
    mma_gemm<<<g1, 128, SM_TOT>>>(zh, wh, opb, attnh, E_DIM);
    // 4) x1 = LN1(x + attn) -> fp16; q -> fp16
    ln1_kernel<<<M_TOK / 8, 256>>>(x, attnh, n1w, n1b, fqp, x1h, qh);
    // 5) ffn = q @ flw^T + flb   (K = 64)
    mma_gemm<<<g1, 128, SM_TOT>>>(qh, w2h, flb, attnh, NQ);
    // 6) out = LN2(x1 + ffn)
    ln2_kernel<<<M_TOK / 8, 256>>>(x1h, attnh, n2w, n2b, out);
}